// round 1
// baseline (speedup 1.0000x reference)
#include <cuda_runtime.h>
#include <math.h>

#define BB 32
#define NN 512
#define FIN 64
#define HH 8
#define HIDD 64
#define OUTF 64

// ---------------- scratch (static __device__, no allocs) ----------------
__device__ float g_Wh   [BB*HH*NN*HIDD];   // layer-1 per-head features
__device__ float g_ssrc [BB*HH*NN];
__device__ float g_sdst [BB*HH*NN];
__device__ float g_vsrc [HH*FIN];          // W_heads @ a_src
__device__ float g_vdst [HH*FIN];
__device__ float g_x    [BB*NN*HH*HIDD];   // layer-1 out, (b,n,h*64+o)
__device__ float g_Wh2  [BB*NN*OUTF];
__device__ float g_s2src[BB*NN];
__device__ float g_s2dst[BB*NN];
__device__ float g_h2   [BB*NN*OUTF];      // layer-2 out == z
__device__ float g_fc1part[32*BB*256];     // split-K partials (deterministic)
__device__ float g_z1   [BB*256];
__device__ float g_z2   [BB*256];

using ull = unsigned long long;

// Blackwell packed fp32x2 FMA (PTX-only pattern; doubles fp32 FMA rate)
__device__ __forceinline__ ull f2pk(float lo, float hi) {
    ull r; asm("mov.b64 %0, {%1, %2};" : "=l"(r) : "f"(lo), "f"(hi)); return r;
}
__device__ __forceinline__ void ffma2(ull& d, ull a, ull b) {
    asm("fma.rn.f32x2 %0, %1, %2, %0;" : "+l"(d) : "l"(a), "l"(b));
}
__device__ __forceinline__ float2 f2un(ull v) {
    float2 r; asm("mov.b64 {%0, %1}, %2;" : "=f"(r.x), "=f"(r.y) : "l"(v)); return r;
}

// ---------------- k_vheads: v = W_heads @ a  (tiny) ----------------
__global__ void k_vheads(const float* __restrict__ Wheads,
                         const float* __restrict__ asrc,
                         const float* __restrict__ adst) {
    int h = blockIdx.x, f = threadIdx.x;         // 8 blocks x 64 threads
    __shared__ float as[64], ad[64];
    as[f] = asrc[h*64 + f]; ad[f] = adst[h*64 + f];
    __syncthreads();
    float s = 0.f, d = 0.f;
    #pragma unroll 16
    for (int o = 0; o < 64; o++) {
        float wv = Wheads[h*4096 + f*64 + o];
        s += wv * as[o]; d += wv * ad[o];
    }
    g_vsrc[h*64 + f] = s; g_vdst[h*64 + f] = d;
}

// ---------------- k_wh1: Wh[b,h,n,o] = feat @ W_heads[h] ----------------
// GEMM M=16384 (b*512+n) x N=64 (per-head tile) x K=64. grid (256 mtiles, 8 h)
__global__ __launch_bounds__(256) void k_wh1(const float* __restrict__ A,
                                             const float* __restrict__ Wheads) {
    __shared__ float At[64][68];   // A^T chunk (pad 68: STS 2-way worst, LDS.128 aligned)
    __shared__ float Bs[64][64];
    int tid = threadIdx.x;
    int m0 = blockIdx.x * 64;
    int h  = blockIdx.y;
    for (int l = tid; l < 1024; l += 256) {      // 1024 float4 = 4096 floats
        int row = l >> 4, f4 = l & 15;
        float4 v = *(const float4*)&A[(size_t)(m0 + row)*64 + f4*4];
        At[f4*4+0][row] = v.x; At[f4*4+1][row] = v.y;
        At[f4*4+2][row] = v.z; At[f4*4+3][row] = v.w;
    }
    for (int l = tid; l < 1024; l += 256) {
        int idx = l * 4;
        *(float4*)&Bs[idx>>6][idx&63] = *(const float4*)&Wheads[h*4096 + idx];
    }
    __syncthreads();
    int ty = tid >> 4, tx = tid & 15;
    ull acc[4][2];
    #pragma unroll
    for (int r = 0; r < 4; r++) { acc[r][0] = 0ULL; acc[r][1] = 0ULL; }
    #pragma unroll 16
    for (int f = 0; f < 64; f++) {
        float4 a4 = *(const float4*)&At[f][ty*4];
        const ull* bp = (const ull*)&Bs[f][tx*4];
        ull b0 = bp[0], b1 = bp[1], p;
        p = f2pk(a4.x, a4.x); ffma2(acc[0][0], p, b0); ffma2(acc[0][1], p, b1);
        p = f2pk(a4.y, a4.y); ffma2(acc[1][0], p, b0); ffma2(acc[1][1], p, b1);
        p = f2pk(a4.z, a4.z); ffma2(acc[2][0], p, b0); ffma2(acc[2][1], p, b1);
        p = f2pk(a4.w, a4.w); ffma2(acc[3][0], p, b0); ffma2(acc[3][1], p, b1);
    }
    #pragma unroll
    for (int r = 0; r < 4; r++) {
        int m = m0 + ty*4 + r;
        int b = m >> 9, n = m & 511;
        float2 v0 = f2un(acc[r][0]), v1 = f2un(acc[r][1]);
        *(float4*)&g_Wh[(((size_t)(b*8 + h))*512 + n)*64 + tx*4] =
            make_float4(v0.x, v0.y, v1.x, v1.y);
    }
}

// ---------------- k_s1: s_src/s_dst = feat . v_{src,dst}[h] ----------------
__global__ __launch_bounds__(256) void k_s1(const float* __restrict__ state) {
    __shared__ float fs[64][65];
    __shared__ float vs[HH][64], vd[HH][64];
    int tid = threadIdx.x, b = blockIdx.x, i0 = blockIdx.y * 64;
    for (int l = tid; l < 512; l += 256) { vs[l>>6][l&63] = g_vsrc[l]; vd[l>>6][l&63] = g_vdst[l]; }
    for (int l = tid; l < 4096; l += 256) {
        int r = l >> 6, f = l & 63;
        fs[r][f] = state[(size_t)b*32768 + (i0 + r)*64 + f];
    }
    __syncthreads();
    int w = tid >> 5, lane = tid & 31;           // warp w -> head w
    #pragma unroll
    for (int rr = 0; rr < 2; rr++) {
        int row = lane + rr*32;
        float as = 0.f, ad = 0.f;
        #pragma unroll 16
        for (int f = 0; f < 64; f++) {
            float fv = fs[row][f];
            as += fv * vs[w][f]; ad += fv * vd[w][f];
        }
        int idx = (b*8 + w)*512 + i0 + row;
        g_ssrc[idx] = as; g_sdst[idx] = ad;
    }
}

// ---------------- k_attn: out = softmax(lrelu(s_i + t_j)) @ Wh ----------------
// register-tiled GEMM with on-the-fly P; f32x2 packed FMA inner loop.
template<int ROWS, bool LAYER2>
__global__ __launch_bounds__(256) void k_attn() {
    constexpr int TR = ROWS / 32;
    __shared__ float s_t[512];
    __shared__ float Wh_s[32][64];
    __shared__ float w_s[ROWS][33];              // col 32 reused for wsum handoff
    __shared__ float red[256];

    const float* WhB  = LAYER2 ? g_Wh2   : g_Wh;
    const float* ssrc = LAYER2 ? g_s2src : g_ssrc;
    const float* sdst = LAYER2 ? g_s2dst : g_sdst;
    float*       outb = LAYER2 ? g_h2    : g_x;
    const int heads   = LAYER2 ? 1 : 8;
    const int rstride = LAYER2 ? 64 : 512;

    int tid = threadIdx.x;
    int g   = blockIdx.y;
    int i0  = blockIdx.x * ROWS;
    const float* Wh = WhB + (size_t)g * NN * 64;
    int b = g / heads, h = g % heads;
    float* outp = outb + (size_t)b * NN * rstride + h * 64;

    s_t[tid]       = sdst[g*NN + tid];
    s_t[tid + 256] = sdst[g*NN + tid + 256];
    red[tid] = fmaxf(s_t[tid], s_t[tid + 256]);
    __syncthreads();
    for (int s = 128; s > 0; s >>= 1) {
        if (tid < s) red[tid] = fmaxf(red[tid], red[tid + s]);
        __syncthreads();
    }
    float tmax = red[0];

    float s_i = 0.f, m_i = 0.f, wsum = 0.f;
    if (tid < ROWS) {
        s_i = ssrc[g*NN + i0 + tid];
        float e = s_i + tmax;                    // lrelu monotone => row max
        m_i = e > 0.f ? e : 0.2f * e;
    }

    int rg = tid >> 3, cg = tid & 7;
    ull acc[TR][4];
    #pragma unroll
    for (int r = 0; r < TR; r++)
        for (int c = 0; c < 4; c++) acc[r][c] = 0ULL;

    for (int jc = 0; jc < NN; jc += 32) {
        __syncthreads();
        {   // load Wh chunk [32][64]
            int base = tid * 8, row = base >> 6, col = base & 63;
            const float4* src = (const float4*)&Wh[(size_t)(jc + row)*64 + col];
            *(float4*)&Wh_s[row][col]     = src[0];
            *(float4*)&Wh_s[row][col + 4] = src[1];
        }
        if (tid < ROWS) {                        // exp weights, once each
            float lsum = 0.f;
            #pragma unroll 8
            for (int jj = 0; jj < 32; jj++) {
                float e = s_i + s_t[jc + jj];
                e = e > 0.f ? e : 0.2f * e;
                float w = __expf(e - m_i);
                w_s[tid][jj] = w;
                lsum += w;
            }
            wsum += lsum;
        }
        __syncthreads();
        #pragma unroll 4
        for (int jj = 0; jj < 32; jj++) {
            const ull* bp = (const ull*)&Wh_s[jj][cg*8];
            ull b0 = bp[0], b1 = bp[1], b2 = bp[2], b3 = bp[3];
            #pragma unroll
            for (int r = 0; r < TR; r++) {
                float wv = w_s[rg*TR + r][jj];
                ull wp = f2pk(wv, wv);
                ffma2(acc[r][0], wp, b0);
                ffma2(acc[r][1], wp, b1);
                ffma2(acc[r][2], wp, b2);
                ffma2(acc[r][3], wp, b3);
            }
        }
    }
    __syncthreads();
    if (tid < ROWS) w_s[tid][32] = wsum;
    __syncthreads();
    #pragma unroll
    for (int r = 0; r < TR; r++) {
        int il = rg*TR + r;
        float inv = __frcp_rn(w_s[il][32]);
        float o8[8];
        #pragma unroll
        for (int c = 0; c < 4; c++) {
            float2 v = f2un(acc[r][c]);
            o8[2*c]   = v.x * inv;
            o8[2*c+1] = v.y * inv;
        }
        if (!LAYER2) {                           // ELU only after layer 1
            #pragma unroll
            for (int c = 0; c < 8; c++) o8[c] = o8[c] > 0.f ? o8[c] : expm1f(o8[c]);
        }
        float* dst = outp + (size_t)(i0 + il) * rstride + cg*8;
        *(float4*)dst       = make_float4(o8[0], o8[1], o8[2], o8[3]);
        *(float4*)(dst + 4) = make_float4(o8[4], o8[5], o8[6], o8[7]);
    }
}

// ---------------- k_gemm2: Wh2 = x @ W_out  (M=16384,N=64,K=512) ----------------
__global__ __launch_bounds__(256) void k_gemm2(const float* __restrict__ Wout) {
    __shared__ float At[64][68];
    __shared__ float Bs[64][64];
    int tid = threadIdx.x, m0 = blockIdx.x * 64;
    int ty = tid >> 4, tx = tid & 15;
    ull acc[4][2];
    #pragma unroll
    for (int r = 0; r < 4; r++) { acc[r][0] = 0ULL; acc[r][1] = 0ULL; }
    for (int k0 = 0; k0 < 512; k0 += 64) {
        __syncthreads();
        for (int l = tid; l < 1024; l += 256) {
            int row = l >> 4, f4 = l & 15;
            float4 v = *(const float4*)&g_x[(size_t)(m0 + row)*512 + k0 + f4*4];
            At[f4*4+0][row] = v.x; At[f4*4+1][row] = v.y;
            At[f4*4+2][row] = v.z; At[f4*4+3][row] = v.w;
        }
        for (int l = tid; l < 1024; l += 256) {
            int idx = l * 4;
            *(float4*)&Bs[idx>>6][idx&63] = *(const float4*)&Wout[(size_t)k0*64 + idx];
        }
        __syncthreads();
        #pragma unroll 16
        for (int f = 0; f < 64; f++) {
            float4 a4 = *(const float4*)&At[f][ty*4];
            const ull* bp = (const ull*)&Bs[f][tx*4];
            ull b0 = bp[0], b1 = bp[1], p;
            p = f2pk(a4.x, a4.x); ffma2(acc[0][0], p, b0); ffma2(acc[0][1], p, b1);
            p = f2pk(a4.y, a4.y); ffma2(acc[1][0], p, b0); ffma2(acc[1][1], p, b1);
            p = f2pk(a4.z, a4.z); ffma2(acc[2][0], p, b0); ffma2(acc[2][1], p, b1);
            p = f2pk(a4.w, a4.w); ffma2(acc[3][0], p, b0); ffma2(acc[3][1], p, b1);
        }
    }
    #pragma unroll
    for (int r = 0; r < 4; r++) {
        float2 v0 = f2un(acc[r][0]), v1 = f2un(acc[r][1]);
        *(float4*)&g_Wh2[(size_t)(m0 + ty*4 + r)*64 + tx*4] =
            make_float4(v0.x, v0.y, v1.x, v1.y);
    }
}

// ---------------- k_s2: s2 = Wh2 . a_out_{src,dst} ----------------
__global__ __launch_bounds__(256) void k_s2(const float* __restrict__ aosrc,
                                            const float* __restrict__ aodst) {
    __shared__ float fs[64][65];
    __shared__ float va[64], vb[64];
    int tid = threadIdx.x, b = blockIdx.x, i0 = blockIdx.y * 64;
    if (tid < 64) { va[tid] = aosrc[tid]; vb[tid] = aodst[tid]; }
    for (int l = tid; l < 4096; l += 256) {
        int r = l >> 6, f = l & 63;
        fs[r][f] = g_Wh2[(size_t)b*32768 + (i0 + r)*64 + f];
    }
    __syncthreads();
    int w = tid >> 5, lane = tid & 31;
    #pragma unroll
    for (int rr = 0; rr < 8; rr++) {
        int row = w*8 + rr;
        float f0 = fs[row][lane], f1 = fs[row][lane + 32];
        float as = f0*va[lane] + f1*va[lane + 32];
        float ad = f0*vb[lane] + f1*vb[lane + 32];
        #pragma unroll
        for (int o = 16; o > 0; o >>= 1) {
            as += __shfl_down_sync(0xffffffffu, as, o);
            ad += __shfl_down_sync(0xffffffffu, ad, o);
        }
        if (lane == 0) {
            g_s2src[b*512 + i0 + row] = as;
            g_s2dst[b*512 + i0 + row] = ad;
        }
    }
}

// ---------------- fc1 split-K (deterministic partials) ----------------
__global__ __launch_bounds__(256) void k_fc1(const float* __restrict__ w1) {
    __shared__ float zs[32][64];
    __shared__ float ws[64][32];
    int tid = threadIdx.x, ct = blockIdx.x, ks = blockIdx.y;
    int cl = tid & 31, rgq = tid >> 5;
    float acc[4] = {0.f, 0.f, 0.f, 0.f};
    int K0 = ks * 1024;
    for (int kc = 0; kc < 1024; kc += 64) {
        __syncthreads();
        for (int l = tid; l < 2048; l += 256) {
            int r = l >> 6, kk = l & 63;
            zs[r][kk] = g_h2[(size_t)r*32768 + K0 + kc + kk];
        }
        for (int l = tid; l < 2048; l += 256) {
            int kk = l >> 5, c = l & 31;
            ws[kk][c] = w1[(size_t)(K0 + kc + kk)*256 + ct*32 + c];
        }
        __syncthreads();
        #pragma unroll 8
        for (int kk = 0; kk < 64; kk++) {
            float wv = ws[kk][cl];
            #pragma unroll
            for (int r = 0; r < 4; r++) acc[r] += zs[rgq*4 + r][kk] * wv;
        }
    }
    #pragma unroll
    for (int r = 0; r < 4; r++)
        g_fc1part[((size_t)ks*32 + rgq*4 + r)*256 + ct*32 + cl] = acc[r];
}

__global__ void k_fc1red(const float* __restrict__ b1) {
    int b = blockIdx.x, c = threadIdx.x;
    float a = 0.f;
    #pragma unroll 8
    for (int ks = 0; ks < 32; ks++) a += g_fc1part[((size_t)ks*32 + b)*256 + c];
    g_z1[b*256 + c] = fmaxf(a + b1[c], 0.f);
}

__global__ void k_fc2(const float* __restrict__ w2, const float* __restrict__ b2) {
    __shared__ float zr[256];
    int b = blockIdx.x, c = threadIdx.x;
    zr[c] = g_z1[b*256 + c];
    __syncthreads();
    float a = 0.f;
    #pragma unroll 8
    for (int k = 0; k < 256; k++) a += zr[k] * w2[(size_t)k*256 + c];
    g_z2[b*256 + c] = fmaxf(a + b2[c], 0.f);
}

__global__ void k_fc3(const float* __restrict__ w3, const float* __restrict__ b3,
                      float* __restrict__ out) {
    int b = blockIdx.x, tid = threadIdx.x;
    int c = tid >> 5, lane = tid & 31;
    float a = 0.f;
    #pragma unroll
    for (int k = lane; k < 256; k += 32) a += g_z2[b*256 + k] * w3[k*4 + c];
    #pragma unroll
    for (int o = 16; o > 0; o >>= 1) a += __shfl_down_sync(0xffffffffu, a, o);
    if (lane == 0) out[b*4 + c] = tanhf(a + b3[c]);
}

// ---------------- launch ----------------
extern "C" void kernel_launch(void* const* d_in, const int* in_sizes, int n_in,
                              void* d_out, int out_size) {
    const float* state  = (const float*)d_in[0];
    const float* Wheads = (const float*)d_in[1];
    const float* asrc   = (const float*)d_in[2];
    const float* adst   = (const float*)d_in[3];
    const float* Wout   = (const float*)d_in[4];
    const float* aosrc  = (const float*)d_in[5];
    const float* aodst  = (const float*)d_in[6];
    const float* w1     = (const float*)d_in[7];
    const float* b1     = (const float*)d_in[8];
    const float* w2     = (const float*)d_in[9];
    const float* b2     = (const float*)d_in[10];
    const float* w3     = (const float*)d_in[11];
    const float* b3     = (const float*)d_in[12];
    float* out = (float*)d_out;

    k_vheads<<<8, 64>>>(Wheads, asrc, adst);
    k_wh1   <<<dim3(256, 8), 256>>>(state, Wheads);
    k_s1    <<<dim3(32, 8), 256>>>(state);
    k_attn<128, false><<<dim3(4, 256), 256>>>();   // layer-1: 1024 blocks
    k_gemm2 <<<256, 256>>>(Wout);
    k_s2    <<<dim3(32, 8), 256>>>(aosrc, aodst);
    k_attn<64, true><<<dim3(8, 32), 256>>>();      // layer-2: 256 blocks
    k_fc1   <<<dim3(8, 32), 256>>>(w1);
    k_fc1red<<<32, 256>>>(b1);
    k_fc2   <<<32, 256>>>(w2, b2);
    k_fc3   <<<32, 128>>>(w3, b3, out);
}

// round 2
// speedup vs baseline: 1.3409x; 1.3409x over previous
#include <cuda_runtime.h>
#include <math.h>

#define BB 32
#define NN 512
#define FIN 64
#define HH 8
#define HIDD 64
#define OUTF 64

// ---------------- scratch (static __device__, no allocs) ----------------
__device__ float g_Wh   [BB*HH*NN*HIDD];   // layer-1 per-head features
__device__ float g_ssrc [BB*HH*NN];
__device__ float g_sdst [BB*HH*NN];
__device__ float g_vsrc [HH*FIN];          // W_heads @ a_src
__device__ float g_vdst [HH*FIN];
__device__ float g_x    [BB*NN*HH*HIDD];   // layer-1 out, (b,n,h*64+o)
__device__ float g_Wh2  [BB*NN*OUTF];
__device__ float g_s2src[BB*NN];
__device__ float g_s2dst[BB*NN];
__device__ float g_h2   [BB*NN*OUTF];      // layer-2 out == z
__device__ float g_fc1part[32*BB*256];     // split-K partials (deterministic)
__device__ float g_z1   [BB*256];
__device__ float g_z2   [BB*256];

using ull = unsigned long long;

// Blackwell packed fp32x2 FMA (PTX-only pattern; doubles fp32 FMA rate)
__device__ __forceinline__ ull f2pk(float lo, float hi) {
    ull r; asm("mov.b64 %0, {%1, %2};" : "=l"(r) : "f"(lo), "f"(hi)); return r;
}
__device__ __forceinline__ void ffma2(ull& d, ull a, ull b) {
    asm("fma.rn.f32x2 %0, %1, %2, %0;" : "+l"(d) : "l"(a), "l"(b));
}
__device__ __forceinline__ float2 f2un(ull v) {
    float2 r; asm("mov.b64 {%0, %1}, %2;" : "=f"(r.x), "=f"(r.y) : "l"(v)); return r;
}

// ---------------- k_vheads: v = W_heads @ a  (tiny) ----------------
__global__ void k_vheads(const float* __restrict__ Wheads,
                         const float* __restrict__ asrc,
                         const float* __restrict__ adst) {
    int h = blockIdx.x, f = threadIdx.x;         // 8 blocks x 64 threads
    __shared__ float as[64], ad[64];
    as[f] = asrc[h*64 + f]; ad[f] = adst[h*64 + f];
    __syncthreads();
    float s = 0.f, d = 0.f;
    #pragma unroll 16
    for (int o = 0; o < 64; o++) {
        float wv = Wheads[h*4096 + f*64 + o];
        s += wv * as[o]; d += wv * ad[o];
    }
    g_vsrc[h*64 + f] = s; g_vdst[h*64 + f] = d;
}

// ---------------- k_wh1: Wh[b,h,n,o] = feat @ W_heads[h] ----------------
__global__ __launch_bounds__(256) void k_wh1(const float* __restrict__ A,
                                             const float* __restrict__ Wheads) {
    __shared__ float At[64][68];
    __shared__ float Bs[64][64];
    int tid = threadIdx.x;
    int m0 = blockIdx.x * 64;
    int h  = blockIdx.y;
    for (int l = tid; l < 1024; l += 256) {
        int row = l >> 4, f4 = l & 15;
        float4 v = *(const float4*)&A[(size_t)(m0 + row)*64 + f4*4];
        At[f4*4+0][row] = v.x; At[f4*4+1][row] = v.y;
        At[f4*4+2][row] = v.z; At[f4*4+3][row] = v.w;
    }
    for (int l = tid; l < 1024; l += 256) {
        int idx = l * 4;
        *(float4*)&Bs[idx>>6][idx&63] = *(const float4*)&Wheads[h*4096 + idx];
    }
    __syncthreads();
    int ty = tid >> 4, tx = tid & 15;
    ull acc[4][2];
    #pragma unroll
    for (int r = 0; r < 4; r++) { acc[r][0] = 0ULL; acc[r][1] = 0ULL; }
    #pragma unroll 16
    for (int f = 0; f < 64; f++) {
        float4 a4 = *(const float4*)&At[f][ty*4];
        const ull* bp = (const ull*)&Bs[f][tx*4];
        ull b0 = bp[0], b1 = bp[1], p;
        p = f2pk(a4.x, a4.x); ffma2(acc[0][0], p, b0); ffma2(acc[0][1], p, b1);
        p = f2pk(a4.y, a4.y); ffma2(acc[1][0], p, b0); ffma2(acc[1][1], p, b1);
        p = f2pk(a4.z, a4.z); ffma2(acc[2][0], p, b0); ffma2(acc[2][1], p, b1);
        p = f2pk(a4.w, a4.w); ffma2(acc[3][0], p, b0); ffma2(acc[3][1], p, b1);
    }
    #pragma unroll
    for (int r = 0; r < 4; r++) {
        int m = m0 + ty*4 + r;
        int b = m >> 9, n = m & 511;
        float2 v0 = f2un(acc[r][0]), v1 = f2un(acc[r][1]);
        *(float4*)&g_Wh[(((size_t)(b*8 + h))*512 + n)*64 + tx*4] =
            make_float4(v0.x, v0.y, v1.x, v1.y);
    }
}

// ---------------- k_s1: s_src/s_dst = feat . v_{src,dst}[h] ----------------
__global__ __launch_bounds__(256) void k_s1(const float* __restrict__ state) {
    __shared__ float fs[64][65];
    __shared__ float vs[HH][64], vd[HH][64];
    int tid = threadIdx.x, b = blockIdx.x, i0 = blockIdx.y * 64;
    for (int l = tid; l < 512; l += 256) { vs[l>>6][l&63] = g_vsrc[l]; vd[l>>6][l&63] = g_vdst[l]; }
    for (int l = tid; l < 4096; l += 256) {
        int r = l >> 6, f = l & 63;
        fs[r][f] = state[(size_t)b*32768 + (i0 + r)*64 + f];
    }
    __syncthreads();
    int w = tid >> 5, lane = tid & 31;
    #pragma unroll
    for (int rr = 0; rr < 2; rr++) {
        int row = lane + rr*32;
        float as = 0.f, ad = 0.f;
        #pragma unroll 16
        for (int f = 0; f < 64; f++) {
            float fv = fs[row][f];
            as += fv * vs[w][f]; ad += fv * vd[w][f];
        }
        int idx = (b*8 + w)*512 + i0 + row;
        g_ssrc[idx] = as; g_sdst[idx] = ad;
    }
}

// ---------------- k_attn v2: out = softmax(lrelu(s_i + t_j)) @ Wh ----------------
// 128 threads, 8x8 thread tile (16 rowgroups x 8 colgroups), packed (w,w) smem,
// double-buffered 16-j chunks with one barrier per chunk.
template<bool LAYER2>
__global__ __launch_bounds__(128) void k_attn2() {
    constexpr int JC = 16;
    __shared__ float s_t[512];
    __shared__ float Whs[2][JC][64];
    __shared__ ull   wpk[2][JC][128];
    __shared__ float red[128];

    const float* WhB  = LAYER2 ? g_Wh2   : g_Wh;
    const float* ssrc = LAYER2 ? g_s2src : g_ssrc;
    const float* sdst = LAYER2 ? g_s2dst : g_sdst;
    float*       outb = LAYER2 ? g_h2    : g_x;
    const int heads   = LAYER2 ? 1 : 8;
    const int rstride = LAYER2 ? 64 : 512;

    int tid = threadIdx.x;
    int g   = blockIdx.y;
    int i0  = blockIdx.x * 128;
    const float* Wh = WhB + (size_t)g * NN * 64;
    int b = g / heads, h = g % heads;
    float* outp = outb + (size_t)b * NN * rstride + h * 64;

    // load s_t + block max
    {
        float a0 = sdst[g*NN + tid];
        float a1 = sdst[g*NN + tid + 128];
        float a2 = sdst[g*NN + tid + 256];
        float a3 = sdst[g*NN + tid + 384];
        s_t[tid] = a0; s_t[tid+128] = a1; s_t[tid+256] = a2; s_t[tid+384] = a3;
        red[tid] = fmaxf(fmaxf(a0, a1), fmaxf(a2, a3));
    }
    __syncthreads();
    for (int s = 64; s > 0; s >>= 1) {
        if (tid < s) red[tid] = fmaxf(red[tid], red[tid + s]);
        __syncthreads();
    }
    float tmax = red[0];
    __syncthreads();

    float s_i = ssrc[g*NN + i0 + tid];
    float e0  = s_i + tmax;                      // lrelu monotone => row max
    float m_i = e0 > 0.f ? e0 : 0.2f * e0;
    float wsum = 0.f;

    int rg = tid >> 3, cg = tid & 7;
    ull acc[8][4];
    #pragma unroll
    for (int r = 0; r < 8; r++)
        #pragma unroll
        for (int c = 0; c < 4; c++) acc[r][c] = 0ULL;

    // producer: fill stage st with chunk starting at jc
    auto fill = [&](int st, int jc) {
        #pragma unroll
        for (int k = 0; k < 2; k++) {
            int idx = tid + k*128;
            int row = idx >> 4, c4 = idx & 15;
            *(float4*)&Whs[st][row][c4*4] =
                *(const float4*)&Wh[(size_t)(jc + row)*64 + c4*4];
        }
        float lsum = 0.f;
        #pragma unroll
        for (int jj = 0; jj < JC; jj++) {
            float e = s_i + s_t[jc + jj];
            e = e > 0.f ? e : 0.2f * e;
            float w = __expf(e - m_i);
            wpk[st][jj][tid] = f2pk(w, w);
            lsum += w;
        }
        wsum += lsum;
    };

    fill(0, 0);
    __syncthreads();
    for (int c = 0; c < 32; c++) {
        int cur = c & 1;
        if (c < 31) fill(cur ^ 1, (c + 1) * JC);
        #pragma unroll
        for (int jj = 0; jj < JC; jj++) {
            const ull* bp = (const ull*)&Whs[cur][jj][cg*8];
            ull b0 = bp[0], b1 = bp[1], b2 = bp[2], b3 = bp[3];
            const ull* wp = &wpk[cur][jj][rg*8];
            #pragma unroll
            for (int r = 0; r < 8; r++) {
                ull w = wp[r];
                ffma2(acc[r][0], w, b0);
                ffma2(acc[r][1], w, b1);
                ffma2(acc[r][2], w, b2);
                ffma2(acc[r][3], w, b3);
            }
        }
        __syncthreads();
    }
    red[tid] = wsum;
    __syncthreads();
    #pragma unroll
    for (int r = 0; r < 8; r++) {
        int row = rg*8 + r;
        float inv = __frcp_rn(red[row]);
        float o8[8];
        #pragma unroll
        for (int c = 0; c < 4; c++) {
            float2 v = f2un(acc[r][c]);
            o8[2*c]   = v.x * inv;
            o8[2*c+1] = v.y * inv;
        }
        if (!LAYER2) {
            #pragma unroll
            for (int c = 0; c < 8; c++) o8[c] = o8[c] > 0.f ? o8[c] : expm1f(o8[c]);
        }
        float* dst = outp + (size_t)(i0 + row) * rstride + cg*8;
        *(float4*)dst       = make_float4(o8[0], o8[1], o8[2], o8[3]);
        *(float4*)(dst + 4) = make_float4(o8[4], o8[5], o8[6], o8[7]);
    }
}

// ---------------- k_gemm2: Wh2 = x @ W_out  (M=16384,N=64,K=512) ----------------
__global__ __launch_bounds__(256) void k_gemm2(const float* __restrict__ Wout) {
    __shared__ float At[64][68];
    __shared__ float Bs[64][64];
    int tid = threadIdx.x, m0 = blockIdx.x * 64;
    int ty = tid >> 4, tx = tid & 15;
    ull acc[4][2];
    #pragma unroll
    for (int r = 0; r < 4; r++) { acc[r][0] = 0ULL; acc[r][1] = 0ULL; }
    for (int k0 = 0; k0 < 512; k0 += 64) {
        __syncthreads();
        for (int l = tid; l < 1024; l += 256) {
            int row = l >> 4, f4 = l & 15;
            float4 v = *(const float4*)&g_x[(size_t)(m0 + row)*512 + k0 + f4*4];
            At[f4*4+0][row] = v.x; At[f4*4+1][row] = v.y;
            At[f4*4+2][row] = v.z; At[f4*4+3][row] = v.w;
        }
        for (int l = tid; l < 1024; l += 256) {
            int idx = l * 4;
            *(float4*)&Bs[idx>>6][idx&63] = *(const float4*)&Wout[(size_t)k0*64 + idx];
        }
        __syncthreads();
        #pragma unroll 16
        for (int f = 0; f < 64; f++) {
            float4 a4 = *(const float4*)&At[f][ty*4];
            const ull* bp = (const ull*)&Bs[f][tx*4];
            ull b0 = bp[0], b1 = bp[1], p;
            p = f2pk(a4.x, a4.x); ffma2(acc[0][0], p, b0); ffma2(acc[0][1], p, b1);
            p = f2pk(a4.y, a4.y); ffma2(acc[1][0], p, b0); ffma2(acc[1][1], p, b1);
            p = f2pk(a4.z, a4.z); ffma2(acc[2][0], p, b0); ffma2(acc[2][1], p, b1);
            p = f2pk(a4.w, a4.w); ffma2(acc[3][0], p, b0); ffma2(acc[3][1], p, b1);
        }
    }
    #pragma unroll
    for (int r = 0; r < 4; r++) {
        float2 v0 = f2un(acc[r][0]), v1 = f2un(acc[r][1]);
        *(float4*)&g_Wh2[(size_t)(m0 + ty*4 + r)*64 + tx*4] =
            make_float4(v0.x, v0.y, v1.x, v1.y);
    }
}

// ---------------- k_s2: s2 = Wh2 . a_out_{src,dst} ----------------
__global__ __launch_bounds__(256) void k_s2(const float* __restrict__ aosrc,
                                            const float* __restrict__ aodst) {
    __shared__ float fs[64][65];
    __shared__ float va[64], vb[64];
    int tid = threadIdx.x, b = blockIdx.x, i0 = blockIdx.y * 64;
    if (tid < 64) { va[tid] = aosrc[tid]; vb[tid] = aodst[tid]; }
    for (int l = tid; l < 4096; l += 256) {
        int r = l >> 6, f = l & 63;
        fs[r][f] = g_Wh2[(size_t)b*32768 + (i0 + r)*64 + f];
    }
    __syncthreads();
    int w = tid >> 5, lane = tid & 31;
    #pragma unroll
    for (int rr = 0; rr < 8; rr++) {
        int row = w*8 + rr;
        float f0 = fs[row][lane], f1 = fs[row][lane + 32];
        float as = f0*va[lane] + f1*va[lane + 32];
        float ad = f0*vb[lane] + f1*vb[lane + 32];
        #pragma unroll
        for (int o = 16; o > 0; o >>= 1) {
            as += __shfl_down_sync(0xffffffffu, as, o);
            ad += __shfl_down_sync(0xffffffffu, ad, o);
        }
        if (lane == 0) {
            g_s2src[b*512 + i0 + row] = as;
            g_s2dst[b*512 + i0 + row] = ad;
        }
    }
}

// ---------------- fc1 split-K (deterministic partials) ----------------
__global__ __launch_bounds__(256) void k_fc1(const float* __restrict__ w1) {
    __shared__ float zs[32][64];
    __shared__ float ws[64][32];
    int tid = threadIdx.x, ct = blockIdx.x, ks = blockIdx.y;
    int cl = tid & 31, rgq = tid >> 5;
    float acc[4] = {0.f, 0.f, 0.f, 0.f};
    int K0 = ks * 1024;
    for (int kc = 0; kc < 1024; kc += 64) {
        __syncthreads();
        for (int l = tid; l < 2048; l += 256) {
            int r = l >> 6, kk = l & 63;
            zs[r][kk] = g_h2[(size_t)r*32768 + K0 + kc + kk];
        }
        for (int l = tid; l < 2048; l += 256) {
            int kk = l >> 5, c = l & 31;
            ws[kk][c] = w1[(size_t)(K0 + kc + kk)*256 + ct*32 + c];
        }
        __syncthreads();
        #pragma unroll 8
        for (int kk = 0; kk < 64; kk++) {
            float wv = ws[kk][cl];
            #pragma unroll
            for (int r = 0; r < 4; r++) acc[r] += zs[rgq*4 + r][kk] * wv;
        }
    }
    #pragma unroll
    for (int r = 0; r < 4; r++)
        g_fc1part[((size_t)ks*32 + rgq*4 + r)*256 + ct*32 + cl] = acc[r];
}

__global__ void k_fc1red(const float* __restrict__ b1) {
    int b = blockIdx.x, c = threadIdx.x;
    float a = 0.f;
    #pragma unroll 8
    for (int ks = 0; ks < 32; ks++) a += g_fc1part[((size_t)ks*32 + b)*256 + c];
    g_z1[b*256 + c] = fmaxf(a + b1[c], 0.f);
}

__global__ void k_fc2(const float* __restrict__ w2, const float* __restrict__ b2) {
    __shared__ float zr[256];
    int b = blockIdx.x, c = threadIdx.x;
    zr[c] = g_z1[b*256 + c];
    __syncthreads();
    float a = 0.f;
    #pragma unroll 8
    for (int k = 0; k < 256; k++) a += zr[k] * w2[(size_t)k*256 + c];
    g_z2[b*256 + c] = fmaxf(a + b2[c], 0.f);
}

__global__ void k_fc3(const float* __restrict__ w3, const float* __restrict__ b3,
                      float* __restrict__ out) {
    int b = blockIdx.x, tid = threadIdx.x;
    int c = tid >> 5, lane = tid & 31;
    float a = 0.f;
    #pragma unroll
    for (int k = lane; k < 256; k += 32) a += g_z2[b*256 + k] * w3[k*4 + c];
    #pragma unroll
    for (int o = 16; o > 0; o >>= 1) a += __shfl_down_sync(0xffffffffu, a, o);
    if (lane == 0) out[b*4 + c] = tanhf(a + b3[c]);
}

// ---------------- launch ----------------
extern "C" void kernel_launch(void* const* d_in, const int* in_sizes, int n_in,
                              void* d_out, int out_size) {
    const float* state  = (const float*)d_in[0];
    const float* Wheads = (const float*)d_in[1];
    const float* asrc   = (const float*)d_in[2];
    const float* adst   = (const float*)d_in[3];
    const float* Wout   = (const float*)d_in[4];
    const float* aosrc  = (const float*)d_in[5];
    const float* aodst  = (const float*)d_in[6];
    const float* w1     = (const float*)d_in[7];
    const float* b1     = (const float*)d_in[8];
    const float* w2     = (const float*)d_in[9];
    const float* b2     = (const float*)d_in[10];
    const float* w3     = (const float*)d_in[11];
    const float* b3     = (const float*)d_in[12];
    float* out = (float*)d_out;

    k_vheads<<<8, 64>>>(Wheads, asrc, adst);
    k_wh1   <<<dim3(256, 8), 256>>>(state, Wheads);
    k_s1    <<<dim3(32, 8), 256>>>(state);
    k_attn2<false><<<dim3(4, 256), 128>>>();   // layer-1
    k_gemm2 <<<256, 256>>>(Wout);
    k_s2    <<<dim3(32, 8), 256>>>(aosrc, aodst);
    k_attn2<true><<<dim3(4, 32), 128>>>();     // layer-2
    k_fc1   <<<dim3(8, 32), 256>>>(w1);
    k_fc1red<<<32, 256>>>(b1);
    k_fc2   <<<32, 256>>>(w2, b2);
    k_fc3   <<<32, 128>>>(w3, b3, out);
}

// round 3
// speedup vs baseline: 1.3522x; 1.0085x over previous
#include <cuda_runtime.h>
#include <math.h>

#define BB 32
#define NN 512
#define FIN 64
#define HH 8
#define HIDD 64
#define OUTF 64

// ---------------- scratch (static __device__, no allocs) ----------------
__device__ float g_Wh   [BB*HH*NN*HIDD];   // layer-1 per-head features
__device__ float g_ssrc [BB*HH*NN];
__device__ float g_sdst [BB*HH*NN];
__device__ float g_vsrc [HH*FIN];          // W_heads @ a_src
__device__ float g_vdst [HH*FIN];
__device__ float g_x    [BB*NN*HH*HIDD];   // layer-1 out, (b,n,h*64+o)
__device__ float g_Wh2  [BB*NN*OUTF];
__device__ float g_s2src[BB*NN];
__device__ float g_s2dst[BB*NN];
__device__ float g_h2   [BB*NN*OUTF];      // layer-2 out == z
__device__ float g_fc1part[32*BB*256];     // split-K partials (deterministic)
__device__ float g_z1   [BB*256];
__device__ float g_z2   [BB*256];

using ull = unsigned long long;

// Blackwell packed fp32x2 FMA (PTX-only pattern; doubles fp32 FMA rate)
__device__ __forceinline__ void ffma2(ull& d, ull a, ull b) {
    asm("fma.rn.f32x2 %0, %1, %2, %0;" : "+l"(d) : "l"(a), "l"(b));
}
__device__ __forceinline__ float2 f2un(ull v) {
    float2 r; asm("mov.b64 {%0, %1}, %2;" : "=f"(r.x), "=f"(r.y) : "l"(v)); return r;
}

// ---------------- k_vheads: v = W_heads @ a  (tiny) ----------------
__global__ void k_vheads(const float* __restrict__ Wheads,
                         const float* __restrict__ asrc,
                         const float* __restrict__ adst) {
    int h = blockIdx.x, f = threadIdx.x;         // 8 blocks x 64 threads
    __shared__ float as[64], ad[64];
    as[f] = asrc[h*64 + f]; ad[f] = adst[h*64 + f];
    __syncthreads();
    float s = 0.f, d = 0.f;
    #pragma unroll 16
    for (int o = 0; o < 64; o++) {
        float wv = Wheads[h*4096 + f*64 + o];
        s += wv * as[o]; d += wv * ad[o];
    }
    g_vsrc[h*64 + f] = s; g_vdst[h*64 + f] = d;
}

// ---------------- k_wh1b: Wh[b,h,n,o] = feat @ W_heads[h] ----------------
// K-pair packed FFMA2: acc = (sum over even k, sum over odd k); no dups/transpose.
// block 128 thr, Mtile 64, N 64, thread tile 8r x 4c.
__global__ __launch_bounds__(128) void k_wh1b(const float* __restrict__ A,
                                              const float* __restrict__ Wheads) {
    __shared__ float As[64][68];
    __shared__ ull   Bp[32][64];     // Bp[kp][c] = (B[2kp][c], B[2kp+1][c])
    int tid = threadIdx.x;
    int m0 = blockIdx.x * 64;
    int h  = blockIdx.y;
    // stage A (row-major, coalesced)
    #pragma unroll
    for (int i = 0; i < 8; i++) {
        int l = tid + i*128, row = l >> 4, f4 = l & 15;
        *(float4*)&As[row][f4*4] = *(const float4*)&A[(size_t)(m0 + row)*64 + f4*4];
    }
    // stage B interleaved pairs
    const float* Bg = Wheads + (size_t)h*4096;
    #pragma unroll
    for (int i = 0; i < 4; i++) {
        int l = tid + i*128, kp = l >> 4, c4 = l & 15;
        float4 f0 = *(const float4*)&Bg[(2*kp  )*64 + c4*4];
        float4 f1 = *(const float4*)&Bg[(2*kp+1)*64 + c4*4];
        *(float4*)&Bp[kp][c4*4]     = make_float4(f0.x, f1.x, f0.y, f1.y);
        *(float4*)&Bp[kp][c4*4 + 2] = make_float4(f0.z, f1.z, f0.w, f1.w);
    }
    __syncthreads();
    int rg = tid >> 4, cg = tid & 15;
    ull acc[8][4];
    #pragma unroll
    for (int r = 0; r < 8; r++)
        #pragma unroll
        for (int c = 0; c < 4; c++) acc[r][c] = 0ULL;
    #pragma unroll 4
    for (int t = 0; t < 16; t++) {
        ulonglong2 b0 = *(const ulonglong2*)&Bp[2*t  ][cg*4];
        ulonglong2 b0b= *(const ulonglong2*)&Bp[2*t  ][cg*4 + 2];
        ulonglong2 b1 = *(const ulonglong2*)&Bp[2*t+1][cg*4];
        ulonglong2 b1b= *(const ulonglong2*)&Bp[2*t+1][cg*4 + 2];
        #pragma unroll
        for (int r = 0; r < 8; r++) {
            ulonglong2 aq = *(const ulonglong2*)&As[rg*8 + r][t*4];
            ffma2(acc[r][0], aq.x, b0.x);  ffma2(acc[r][1], aq.x, b0.y);
            ffma2(acc[r][2], aq.x, b0b.x); ffma2(acc[r][3], aq.x, b0b.y);
            ffma2(acc[r][0], aq.y, b1.x);  ffma2(acc[r][1], aq.y, b1.y);
            ffma2(acc[r][2], aq.y, b1b.x); ffma2(acc[r][3], aq.y, b1b.y);
        }
    }
    #pragma unroll
    for (int r = 0; r < 8; r++) {
        int m = m0 + rg*8 + r;
        int b = m >> 9, n = m & 511;
        float4 o;
        float2 v0 = f2un(acc[r][0]), v1 = f2un(acc[r][1]);
        float2 v2 = f2un(acc[r][2]), v3 = f2un(acc[r][3]);
        o.x = v0.x + v0.y; o.y = v1.x + v1.y; o.z = v2.x + v2.y; o.w = v3.x + v3.y;
        *(float4*)&g_Wh[(((size_t)(b*8 + h))*512 + n)*64 + cg*4] = o;
    }
}

// ---------------- k_s1: s_src/s_dst = feat . v_{src,dst}[h] ----------------
__global__ __launch_bounds__(256) void k_s1(const float* __restrict__ state) {
    __shared__ float fs[64][65];
    __shared__ float vs[HH][64], vd[HH][64];
    int tid = threadIdx.x, b = blockIdx.x, i0 = blockIdx.y * 64;
    for (int l = tid; l < 512; l += 256) { vs[l>>6][l&63] = g_vsrc[l]; vd[l>>6][l&63] = g_vdst[l]; }
    for (int l = tid; l < 4096; l += 256) {
        int r = l >> 6, f = l & 63;
        fs[r][f] = state[(size_t)b*32768 + (i0 + r)*64 + f];
    }
    __syncthreads();
    int w = tid >> 5, lane = tid & 31;
    #pragma unroll
    for (int rr = 0; rr < 2; rr++) {
        int row = lane + rr*32;
        float as = 0.f, ad = 0.f;
        #pragma unroll 16
        for (int f = 0; f < 64; f++) {
            float fv = fs[row][f];
            as += fv * vs[w][f]; ad += fv * vd[w][f];
        }
        int idx = (b*8 + w)*512 + i0 + row;
        g_ssrc[idx] = as; g_sdst[idx] = ad;
    }
}

// ---------------- k_attn4: out = softmax(lrelu(s_i + t_j)) @ Wh ----------------
// K-pair packing along j: acc halves = (even-j sum, odd-j sum). No dup MOVs.
// block 128 thr, 64 rows/block, thread tile 8r x 4c. Double-buffered 16-j chunks.
template<bool LAYER2>
__global__ __launch_bounds__(128) void k_attn4() {
    __shared__ float s_t[512];
    __shared__ ull   Whp[2][8][64];   // [stage][jp][c] = (Wh[2j][c], Wh[2j+1][c])
    __shared__ float w_s[2][64][16];  // [stage][row][jj]
    __shared__ float red[128];

    const float* WhB  = LAYER2 ? g_Wh2   : g_Wh;
    const float* ssrc = LAYER2 ? g_s2src : g_ssrc;
    const float* sdst = LAYER2 ? g_s2dst : g_sdst;
    float*       outb = LAYER2 ? g_h2    : g_x;
    const int heads   = LAYER2 ? 1 : 8;
    const int rstride = LAYER2 ? 64 : 512;

    int tid = threadIdx.x;
    int g   = blockIdx.y;
    int i0  = blockIdx.x * 64;
    const float* Wh = WhB + (size_t)g * NN * 64;
    int b = g / heads, h = g % heads;
    float* outp = outb + (size_t)b * NN * rstride + h * 64;

    // load s_t + block max
    {
        float a0 = sdst[g*NN + tid];
        float a1 = sdst[g*NN + tid + 128];
        float a2 = sdst[g*NN + tid + 256];
        float a3 = sdst[g*NN + tid + 384];
        s_t[tid] = a0; s_t[tid+128] = a1; s_t[tid+256] = a2; s_t[tid+384] = a3;
        red[tid] = fmaxf(fmaxf(a0, a1), fmaxf(a2, a3));
    }
    __syncthreads();
    for (int s = 64; s > 0; s >>= 1) {
        if (tid < s) red[tid] = fmaxf(red[tid], red[tid + s]);
        __syncthreads();
    }
    float tmax = red[0];
    __syncthreads();

    int row_f = tid >> 1;                 // fill row (two threads per row)
    int jh    = (tid & 1) * 8;            // fill jj half
    float s_i = ssrc[g*NN + i0 + row_f];
    float e0  = s_i + tmax;               // lrelu monotone => row max
    float m_i = e0 > 0.f ? e0 : 0.2f * e0;
    float wsum = 0.f;

    int rg = tid >> 4, cg = tid & 15;
    ull acc[8][4];
    #pragma unroll
    for (int r = 0; r < 8; r++)
        #pragma unroll
        for (int c = 0; c < 4; c++) acc[r][c] = 0ULL;

    auto fill = [&](int st, int jc) {
        // Whp interleave: thread -> (jp, c4)
        int jp = tid >> 4, c4 = tid & 15;
        float4 f0 = *(const float4*)&Wh[(size_t)(jc + 2*jp    )*64 + c4*4];
        float4 f1 = *(const float4*)&Wh[(size_t)(jc + 2*jp + 1)*64 + c4*4];
        *(float4*)&Whp[st][jp][c4*4]     = make_float4(f0.x, f1.x, f0.y, f1.y);
        *(float4*)&Whp[st][jp][c4*4 + 2] = make_float4(f0.z, f1.z, f0.w, f1.w);
        // weights (each exp exactly once)
        float wv[8]; float lsum = 0.f;
        #pragma unroll
        for (int k = 0; k < 8; k++) {
            float e = s_i + s_t[jc + jh + k];
            e = e > 0.f ? e : 0.2f * e;
            float w = __expf(e - m_i);
            wv[k] = w; lsum += w;
        }
        *(float4*)&w_s[st][row_f][jh]     = make_float4(wv[0], wv[1], wv[2], wv[3]);
        *(float4*)&w_s[st][row_f][jh + 4] = make_float4(wv[4], wv[5], wv[6], wv[7]);
        wsum += lsum;
    };

    fill(0, 0);
    __syncthreads();
    for (int c = 0; c < 32; c++) {
        int cur = c & 1;
        if (c < 31) fill(cur ^ 1, (c + 1) * 16);
        #pragma unroll
        for (int t = 0; t < 4; t++) {      // covers jp = 2t, 2t+1 (4 j's)
            ulonglong2 b0 = *(const ulonglong2*)&Whp[cur][2*t  ][cg*4];
            ulonglong2 b0b= *(const ulonglong2*)&Whp[cur][2*t  ][cg*4 + 2];
            ulonglong2 b1 = *(const ulonglong2*)&Whp[cur][2*t+1][cg*4];
            ulonglong2 b1b= *(const ulonglong2*)&Whp[cur][2*t+1][cg*4 + 2];
            #pragma unroll
            for (int r = 0; r < 8; r++) {
                ulonglong2 wq = *(const ulonglong2*)&w_s[cur][rg*8 + r][t*4];
                ffma2(acc[r][0], wq.x, b0.x);  ffma2(acc[r][1], wq.x, b0.y);
                ffma2(acc[r][2], wq.x, b0b.x); ffma2(acc[r][3], wq.x, b0b.y);
                ffma2(acc[r][0], wq.y, b1.x);  ffma2(acc[r][1], wq.y, b1.y);
                ffma2(acc[r][2], wq.y, b1b.x); ffma2(acc[r][3], wq.y, b1b.y);
            }
        }
        __syncthreads();
    }
    // row sums: combine the two half-sums per row
    wsum += __shfl_xor_sync(0xffffffffu, wsum, 1);
    if ((tid & 1) == 0) red[row_f] = wsum;
    __syncthreads();
    #pragma unroll
    for (int r = 0; r < 8; r++) {
        int row = rg*8 + r;
        float inv = __frcp_rn(red[row]);
        float2 v0 = f2un(acc[r][0]), v1 = f2un(acc[r][1]);
        float2 v2 = f2un(acc[r][2]), v3 = f2un(acc[r][3]);
        float o0 = (v0.x + v0.y) * inv;
        float o1 = (v1.x + v1.y) * inv;
        float o2 = (v2.x + v2.y) * inv;
        float o3 = (v3.x + v3.y) * inv;
        if (!LAYER2) {
            o0 = o0 > 0.f ? o0 : expm1f(o0);
            o1 = o1 > 0.f ? o1 : expm1f(o1);
            o2 = o2 > 0.f ? o2 : expm1f(o2);
            o3 = o3 > 0.f ? o3 : expm1f(o3);
        }
        *(float4*)&outp[(size_t)(i0 + row) * rstride + cg*4] =
            make_float4(o0, o1, o2, o3);
    }
}

// ---------------- k_gemm2b: Wh2 = x @ W_out  (M=16384,N=64,K=512) ----------------
__global__ __launch_bounds__(128) void k_gemm2b(const float* __restrict__ Wout) {
    __shared__ float As[64][68];
    __shared__ ull   Bp[32][64];
    int tid = threadIdx.x, m0 = blockIdx.x * 64;
    int rg = tid >> 4, cg = tid & 15;
    ull acc[8][4];
    #pragma unroll
    for (int r = 0; r < 8; r++)
        #pragma unroll
        for (int c = 0; c < 4; c++) acc[r][c] = 0ULL;
    for (int k0 = 0; k0 < 512; k0 += 64) {
        __syncthreads();
        #pragma unroll
        for (int i = 0; i < 8; i++) {
            int l = tid + i*128, row = l >> 4, f4 = l & 15;
            *(float4*)&As[row][f4*4] =
                *(const float4*)&g_x[(size_t)(m0 + row)*512 + k0 + f4*4];
        }
        #pragma unroll
        for (int i = 0; i < 4; i++) {
            int l = tid + i*128, kp = l >> 4, c4 = l & 15;
            float4 f0 = *(const float4*)&Wout[(size_t)(k0 + 2*kp    )*64 + c4*4];
            float4 f1 = *(const float4*)&Wout[(size_t)(k0 + 2*kp + 1)*64 + c4*4];
            *(float4*)&Bp[kp][c4*4]     = make_float4(f0.x, f1.x, f0.y, f1.y);
            *(float4*)&Bp[kp][c4*4 + 2] = make_float4(f0.z, f1.z, f0.w, f1.w);
        }
        __syncthreads();
        #pragma unroll 4
        for (int t = 0; t < 16; t++) {
            ulonglong2 b0 = *(const ulonglong2*)&Bp[2*t  ][cg*4];
            ulonglong2 b0b= *(const ulonglong2*)&Bp[2*t  ][cg*4 + 2];
            ulonglong2 b1 = *(const ulonglong2*)&Bp[2*t+1][cg*4];
            ulonglong2 b1b= *(const ulonglong2*)&Bp[2*t+1][cg*4 + 2];
            #pragma unroll
            for (int r = 0; r < 8; r++) {
                ulonglong2 aq = *(const ulonglong2*)&As[rg*8 + r][t*4];
                ffma2(acc[r][0], aq.x, b0.x);  ffma2(acc[r][1], aq.x, b0.y);
                ffma2(acc[r][2], aq.x, b0b.x); ffma2(acc[r][3], aq.x, b0b.y);
                ffma2(acc[r][0], aq.y, b1.x);  ffma2(acc[r][1], aq.y, b1.y);
                ffma2(acc[r][2], aq.y, b1b.x); ffma2(acc[r][3], aq.y, b1b.y);
            }
        }
    }
    #pragma unroll
    for (int r = 0; r < 8; r++) {
        float4 o;
        float2 v0 = f2un(acc[r][0]), v1 = f2un(acc[r][1]);
        float2 v2 = f2un(acc[r][2]), v3 = f2un(acc[r][3]);
        o.x = v0.x + v0.y; o.y = v1.x + v1.y; o.z = v2.x + v2.y; o.w = v3.x + v3.y;
        *(float4*)&g_Wh2[(size_t)(m0 + rg*8 + r)*64 + cg*4] = o;
    }
}

// ---------------- k_s2: s2 = Wh2 . a_out_{src,dst} ----------------
__global__ __launch_bounds__(256) void k_s2(const float* __restrict__ aosrc,
                                            const float* __restrict__ aodst) {
    __shared__ float fs[64][65];
    __shared__ float va[64], vb[64];
    int tid = threadIdx.x, b = blockIdx.x, i0 = blockIdx.y * 64;
    if (tid < 64) { va[tid] = aosrc[tid]; vb[tid] = aodst[tid]; }
    for (int l = tid; l < 4096; l += 256) {
        int r = l >> 6, f = l & 63;
        fs[r][f] = g_Wh2[(size_t)b*32768 + (i0 + r)*64 + f];
    }
    __syncthreads();
    int w = tid >> 5, lane = tid & 31;
    #pragma unroll
    for (int rr = 0; rr < 8; rr++) {
        int row = w*8 + rr;
        float f0 = fs[row][lane], f1 = fs[row][lane + 32];
        float as = f0*va[lane] + f1*va[lane + 32];
        float ad = f0*vb[lane] + f1*vb[lane + 32];
        #pragma unroll
        for (int o = 16; o > 0; o >>= 1) {
            as += __shfl_down_sync(0xffffffffu, as, o);
            ad += __shfl_down_sync(0xffffffffu, ad, o);
        }
        if (lane == 0) {
            g_s2src[b*512 + i0 + row] = as;
            g_s2dst[b*512 + i0 + row] = ad;
        }
    }
}

// ---------------- fc1 split-K (deterministic partials) ----------------
__global__ __launch_bounds__(256) void k_fc1(const float* __restrict__ w1) {
    __shared__ float zs[32][64];
    __shared__ float ws[64][32];
    int tid = threadIdx.x, ct = blockIdx.x, ks = blockIdx.y;
    int cl = tid & 31, rgq = tid >> 5;
    float acc[4] = {0.f, 0.f, 0.f, 0.f};
    int K0 = ks * 1024;
    for (int kc = 0; kc < 1024; kc += 64) {
        __syncthreads();
        for (int l = tid; l < 2048; l += 256) {
            int r = l >> 6, kk = l & 63;
            zs[r][kk] = g_h2[(size_t)r*32768 + K0 + kc + kk];
        }
        for (int l = tid; l < 2048; l += 256) {
            int kk = l >> 5, c = l & 31;
            ws[kk][c] = w1[(size_t)(K0 + kc + kk)*256 + ct*32 + c];
        }
        __syncthreads();
        #pragma unroll 8
        for (int kk = 0; kk < 64; kk++) {
            float wv = ws[kk][cl];
            #pragma unroll
            for (int r = 0; r < 4; r++) acc[r] += zs[rgq*4 + r][kk] * wv;
        }
    }
    #pragma unroll
    for (int r = 0; r < 4; r++)
        g_fc1part[((size_t)ks*32 + rgq*4 + r)*256 + ct*32 + cl] = acc[r];
}

__global__ void k_fc1red(const float* __restrict__ b1) {
    int b = blockIdx.x, c = threadIdx.x;
    float a = 0.f;
    #pragma unroll 8
    for (int ks = 0; ks < 32; ks++) a += g_fc1part[((size_t)ks*32 + b)*256 + c];
    g_z1[b*256 + c] = fmaxf(a + b1[c], 0.f);
}

__global__ void k_fc2(const float* __restrict__ w2, const float* __restrict__ b2) {
    __shared__ float zr[256];
    int b = blockIdx.x, c = threadIdx.x;
    zr[c] = g_z1[b*256 + c];
    __syncthreads();
    float a = 0.f;
    #pragma unroll 8
    for (int k = 0; k < 256; k++) a += zr[k] * w2[(size_t)k*256 + c];
    g_z2[b*256 + c] = fmaxf(a + b2[c], 0.f);
}

__global__ void k_fc3(const float* __restrict__ w3, const float* __restrict__ b3,
                      float* __restrict__ out) {
    int b = blockIdx.x, tid = threadIdx.x;
    int c = tid >> 5, lane = tid & 31;
    float a = 0.f;
    #pragma unroll
    for (int k = lane; k < 256; k += 32) a += g_z2[b*256 + k] * w3[k*4 + c];
    #pragma unroll
    for (int o = 16; o > 0; o >>= 1) a += __shfl_down_sync(0xffffffffu, a, o);
    if (lane == 0) out[b*4 + c] = tanhf(a + b3[c]);
}

// ---------------- launch ----------------
extern "C" void kernel_launch(void* const* d_in, const int* in_sizes, int n_in,
                              void* d_out, int out_size) {
    const float* state  = (const float*)d_in[0];
    const float* Wheads = (const float*)d_in[1];
    const float* asrc   = (const float*)d_in[2];
    const float* adst   = (const float*)d_in[3];
    const float* Wout   = (const float*)d_in[4];
    const float* aosrc  = (const float*)d_in[5];
    const float* aodst  = (const float*)d_in[6];
    const float* w1     = (const float*)d_in[7];
    const float* b1     = (const float*)d_in[8];
    const float* w2     = (const float*)d_in[9];
    const float* b2     = (const float*)d_in[10];
    const float* w3     = (const float*)d_in[11];
    const float* b3     = (const float*)d_in[12];
    float* out = (float*)d_out;

    k_vheads<<<8, 64>>>(Wheads, asrc, adst);
    k_wh1b  <<<dim3(256, 8), 128>>>(state, Wheads);
    k_s1    <<<dim3(32, 8), 256>>>(state);
    k_attn4<false><<<dim3(8, 256), 128>>>();   // layer-1: 2048 blocks
    k_gemm2b<<<256, 128>>>(Wout);
    k_s2    <<<dim3(32, 8), 256>>>(aosrc, aodst);
    k_attn4<true><<<dim3(8, 32), 128>>>();     // layer-2: 256 blocks
    k_fc1   <<<dim3(8, 32), 256>>>(w1);
    k_fc1red<<<32, 256>>>(b1);
    k_fc2   <<<32, 256>>>(w2, b2);
    k_fc3   <<<32, 128>>>(w3, b3, out);
}

// round 9
// speedup vs baseline: 2.1135x; 1.5630x over previous
#include <cuda_runtime.h>
#include <cuda_fp16.h>
#include <math.h>
#include <stdint.h>

#define BB 32
#define NN 512
#define FIN 64
#define HH 8
#define HIDD 64
#define OUTF 64

// ---------------- scratch (static __device__, no allocs) ----------------
__device__ uint32_t g_WhT_hi[BB*HH*64*256];  // layer-1 Wh^T, fp16-pair hi (per bh: [n=64][kpair=256])
__device__ uint32_t g_WhT_lo[BB*HH*64*256];  // fp16-pair lo (residual)
__device__ float g_ssrc [BB*HH*NN];
__device__ float g_sdst [BB*HH*NN];
__device__ float g_vsrc [HH*FIN];
__device__ float g_vdst [HH*FIN];
__device__ float g_x    [BB*NN*HH*HIDD];     // layer-1 out, (b,n,h*64+o)
__device__ float g_Wh2  [BB*NN*OUTF];        // normal layout (for k_s2)
__device__ uint32_t g_Wh2T_hi[BB*64*256];    // layer-2 Wh2^T fp16-pair hi
__device__ uint32_t g_Wh2T_lo[BB*64*256];
__device__ float g_s2src[BB*NN];
__device__ float g_s2dst[BB*NN];
__device__ float g_h2   [BB*NN*OUTF];        // layer-2 out == z
__device__ float g_fc1part[32*BB*256];
__device__ float g_z1   [BB*256];
__device__ float g_z2   [BB*256];

using ull = unsigned long long;

__device__ __forceinline__ void ffma2(ull& d, ull a, ull b) {
    asm("fma.rn.f32x2 %0, %1, %2, %0;" : "+l"(d) : "l"(a), "l"(b));
}
__device__ __forceinline__ float2 f2un(ull v) {
    float2 r; asm("mov.b64 {%0, %1}, %2;" : "=f"(r.x), "=f"(r.y) : "l"(v)); return r;
}

// fp16 error-split: (w0,w1) -> hi pair + lo pair (packed f16x2, even k in low half)
__device__ __forceinline__ void split16(float w0, float w1, uint32_t& hi, uint32_t& lo) {
    __half h0 = __float2half_rn(w0), h1 = __float2half_rn(w1);
    __half2 H = __halves2half2(h0, h1);
    hi = *reinterpret_cast<uint32_t*>(&H);
    float r0 = w0 - __half2float(h0);
    float r1 = w1 - __half2float(h1);
    __half2 L = __halves2half2(__float2half_rn(r0), __float2half_rn(r1));
    lo = *reinterpret_cast<uint32_t*>(&L);
}

// warp MMA: D(16x8,f32) += A(16x16,f16) * B(16x8,f16)
__device__ __forceinline__ void mma16816(float* c, const uint32_t* a, uint32_t b0, uint32_t b1) {
    asm volatile(
        "mma.sync.aligned.m16n8k16.row.col.f32.f16.f16.f32 "
        "{%0,%1,%2,%3}, {%4,%5,%6,%7}, {%8,%9}, {%0,%1,%2,%3};"
        : "+f"(c[0]), "+f"(c[1]), "+f"(c[2]), "+f"(c[3])
        : "r"(a[0]), "r"(a[1]), "r"(a[2]), "r"(a[3]), "r"(b0), "r"(b1));
}

// ---------------- k_vheads ----------------
__global__ void k_vheads(const float* __restrict__ Wheads,
                         const float* __restrict__ asrc,
                         const float* __restrict__ adst) {
    int h = blockIdx.x, f = threadIdx.x;
    __shared__ float as[64], ad[64];
    as[f] = asrc[h*64 + f]; ad[f] = adst[h*64 + f];
    __syncthreads();
    float s = 0.f, d = 0.f;
    #pragma unroll 16
    for (int o = 0; o < 64; o++) {
        float wv = Wheads[h*4096 + f*64 + o];
        s += wv * as[o]; d += wv * ad[o];
    }
    g_vsrc[h*64 + f] = s; g_vdst[h*64 + f] = d;
}

// ---------------- k_wh1b: Wh = feat @ W_heads[h] -> transposed fp16-split ----------------
__global__ __launch_bounds__(128) void k_wh1b(const float* __restrict__ A,
                                              const float* __restrict__ Wheads) {
    __shared__ float As[64][68];
    __shared__ ull   Bp[32][64];
    int tid = threadIdx.x;
    int m0 = blockIdx.x * 64;
    int h  = blockIdx.y;
    #pragma unroll
    for (int i = 0; i < 8; i++) {
        int l = tid + i*128, row = l >> 4, f4 = l & 15;
        *(float4*)&As[row][f4*4] = *(const float4*)&A[(size_t)(m0 + row)*64 + f4*4];
    }
    const float* Bg = Wheads + (size_t)h*4096;
    #pragma unroll
    for (int i = 0; i < 4; i++) {
        int l = tid + i*128, kp = l >> 4, c4 = l & 15;
        float4 f0 = *(const float4*)&Bg[(2*kp  )*64 + c4*4];
        float4 f1 = *(const float4*)&Bg[(2*kp+1)*64 + c4*4];
        *(float4*)&Bp[kp][c4*4]     = make_float4(f0.x, f1.x, f0.y, f1.y);
        *(float4*)&Bp[kp][c4*4 + 2] = make_float4(f0.z, f1.z, f0.w, f1.w);
    }
    __syncthreads();
    int rg = tid >> 4, cg = tid & 15;
    ull acc[8][4];
    #pragma unroll
    for (int r = 0; r < 8; r++)
        #pragma unroll
        for (int c = 0; c < 4; c++) acc[r][c] = 0ULL;
    #pragma unroll 4
    for (int t = 0; t < 16; t++) {
        ulonglong2 b0 = *(const ulonglong2*)&Bp[2*t  ][cg*4];
        ulonglong2 b0b= *(const ulonglong2*)&Bp[2*t  ][cg*4 + 2];
        ulonglong2 b1 = *(const ulonglong2*)&Bp[2*t+1][cg*4];
        ulonglong2 b1b= *(const ulonglong2*)&Bp[2*t+1][cg*4 + 2];
        #pragma unroll
        for (int r = 0; r < 8; r++) {
            ulonglong2 aq = *(const ulonglong2*)&As[rg*8 + r][t*4];
            ffma2(acc[r][0], aq.x, b0.x);  ffma2(acc[r][1], aq.x, b0.y);
            ffma2(acc[r][2], aq.x, b0b.x); ffma2(acc[r][3], aq.x, b0b.y);
            ffma2(acc[r][0], aq.y, b1.x);  ffma2(acc[r][1], aq.y, b1.y);
            ffma2(acc[r][2], aq.y, b1b.x); ffma2(acc[r][3], aq.y, b1b.y);
        }
    }
    float o[8][4];
    #pragma unroll
    for (int r = 0; r < 8; r++) {
        float2 v0 = f2un(acc[r][0]), v1 = f2un(acc[r][1]);
        float2 v2 = f2un(acc[r][2]), v3 = f2un(acc[r][3]);
        o[r][0] = v0.x + v0.y; o[r][1] = v1.x + v1.y;
        o[r][2] = v2.x + v2.y; o[r][3] = v3.x + v3.y;
    }
    int jb = (m0 & 511) + rg*8;         // j index (even), 8 consecutive
    int bh = (m0 >> 9)*8 + h;
    #pragma unroll
    for (int q = 0; q < 4; q++) {
        int n = cg*4 + q;
        uint4 Hv, Lv;
        split16(o[0][q], o[1][q], Hv.x, Lv.x);
        split16(o[2][q], o[3][q], Hv.y, Lv.y);
        split16(o[4][q], o[5][q], Hv.z, Lv.z);
        split16(o[6][q], o[7][q], Hv.w, Lv.w);
        size_t idx = ((size_t)bh*64 + n)*256 + (jb >> 1);
        *(uint4*)&g_WhT_hi[idx] = Hv;
        *(uint4*)&g_WhT_lo[idx] = Lv;
    }
}

// ---------------- k_s1 ----------------
__global__ __launch_bounds__(256) void k_s1(const float* __restrict__ state) {
    __shared__ float fs[64][65];
    __shared__ float vs[HH][64], vd[HH][64];
    int tid = threadIdx.x, b = blockIdx.x, i0 = blockIdx.y * 64;
    for (int l = tid; l < 512; l += 256) { vs[l>>6][l&63] = g_vsrc[l]; vd[l>>6][l&63] = g_vdst[l]; }
    for (int l = tid; l < 4096; l += 256) {
        int r = l >> 6, f = l & 63;
        fs[r][f] = state[(size_t)b*32768 + (i0 + r)*64 + f];
    }
    __syncthreads();
    int w = tid >> 5, lane = tid & 31;
    #pragma unroll
    for (int rr = 0; rr < 2; rr++) {
        int row = lane + rr*32;
        float as = 0.f, ad = 0.f;
        #pragma unroll 16
        for (int f = 0; f < 64; f++) {
            float fv = fs[row][f];
            as += fv * vs[w][f]; ad += fv * vd[w][f];
        }
        int idx = (b*8 + w)*512 + i0 + row;
        g_ssrc[idx] = as; g_sdst[idx] = ad;
    }
}

// ---------------- k_attn_mma: softmax(lrelu(s_i+t_j)) @ Wh via mma.sync f16-split ----------------
// Block: 128 thr (4 warps), 128 rows x 64 cols per block. Warp tile 32r x 64c
// (2 row-tiles x 8 col-tiles of m16n8k16). A (P weights) built in fragment regs.
template<bool LAYER2>
__global__ __launch_bounds__(128) void k_attn_mma() {
    __shared__ float s_t[512];
    __shared__ float red[32];
    __shared__ uint32_t sBh[64*36];      // stride 36 words: conflict-free frag loads
    __shared__ uint32_t sBl[64*36];

    const float* ssrc = LAYER2 ? g_s2src : g_ssrc;
    const float* sdst = LAYER2 ? g_s2dst : g_sdst;
    const uint32_t* BhG0 = LAYER2 ? g_Wh2T_hi : g_WhT_hi;
    const uint32_t* BlG0 = LAYER2 ? g_Wh2T_lo : g_WhT_lo;
    float*       outb = LAYER2 ? g_h2    : g_x;
    const int heads   = LAYER2 ? 1 : 8;
    const int rstride = LAYER2 ? 64 : 512;

    int tid = threadIdx.x, wid = tid >> 5, lane = tid & 31;
    int g = lane >> 2, t = lane & 3;
    int grp = blockIdx.y;
    int i0  = blockIdx.x * 128;
    const uint32_t* BhG = BhG0 + (size_t)grp * 16384;
    const uint32_t* BlG = BlG0 + (size_t)grp * 16384;
    int b = grp / heads, h = grp % heads;
    float* outp = outb + (size_t)b * NN * rstride + h * 64;

    // s_t + block max
    {
        float a0 = sdst[grp*NN + tid];
        float a1 = sdst[grp*NN + tid + 128];
        float a2 = sdst[grp*NN + tid + 256];
        float a3 = sdst[grp*NN + tid + 384];
        s_t[tid] = a0; s_t[tid+128] = a1; s_t[tid+256] = a2; s_t[tid+384] = a3;
        float m = fmaxf(fmaxf(a0, a1), fmaxf(a2, a3));
        #pragma unroll
        for (int o = 16; o > 0; o >>= 1) m = fmaxf(m, __shfl_xor_sync(0xffffffffu, m, o));
        if (lane == 0) red[wid] = m;
    }
    __syncthreads();
    float tmax = fmaxf(fmaxf(red[0], red[1]), fmaxf(red[2], red[3]));

    // per-thread rows: g, g+8, g+16, g+24 (warp-local)
    float si[4], mi[4];
    #pragma unroll
    for (int r = 0; r < 4; r++) {
        int row = i0 + wid*32 + g + r*8;
        si[r] = ssrc[grp*NN + row];
        float e = si[r] + tmax;             // lrelu monotone => row max
        mi[r] = e > 0.f ? e : 0.2f * e;
    }

    float C[2][8][4];
    #pragma unroll
    for (int rt = 0; rt < 2; rt++)
        #pragma unroll
        for (int ct = 0; ct < 8; ct++)
            #pragma unroll
            for (int q = 0; q < 4; q++) C[rt][ct][q] = 0.f;
    float wsum[4] = {0.f, 0.f, 0.f, 0.f};

    for (int c = 0; c < 8; c++) {
        __syncthreads();
        // stage B chunk (64 n x 32 kpairs), hi + lo
        #pragma unroll
        for (int i = 0; i < 4; i++) {
            int lin = tid + i*128;
            int n = lin >> 3, q4 = lin & 7;
            *(uint4*)&sBh[n*36 + q4*4] = *(const uint4*)(BhG + (size_t)n*256 + c*32 + q4*4);
            *(uint4*)&sBl[n*36 + q4*4] = *(const uint4*)(BlG + (size_t)n*256 + c*32 + q4*4);
        }
        __syncthreads();
        #pragma unroll
        for (int ks = 0; ks < 4; ks++) {
            int k0 = c*64 + ks*16;
            float st0 = s_t[k0 + 2*t],     st1 = s_t[k0 + 2*t + 1];
            float st2 = s_t[k0 + 2*t + 8], st3 = s_t[k0 + 2*t + 9];
            uint32_t ah[2][4], al[2][4];
            #pragma unroll
            for (int rt = 0; rt < 2; rt++) {
                float siA = si[rt*2], miA = mi[rt*2];
                float siB = si[rt*2+1], miB = mi[rt*2+1];
                float e, w00, w01, w02, w03, w10, w11, w12, w13;
                e = siA + st0; e = e > 0.f ? e : 0.2f*e; w00 = __expf(e - miA);
                e = siA + st1; e = e > 0.f ? e : 0.2f*e; w01 = __expf(e - miA);
                e = siA + st2; e = e > 0.f ? e : 0.2f*e; w02 = __expf(e - miA);
                e = siA + st3; e = e > 0.f ? e : 0.2f*e; w03 = __expf(e - miA);
                e = siB + st0; e = e > 0.f ? e : 0.2f*e; w10 = __expf(e - miB);
                e = siB + st1; e = e > 0.f ? e : 0.2f*e; w11 = __expf(e - miB);
                e = siB + st2; e = e > 0.f ? e : 0.2f*e; w12 = __expf(e - miB);
                e = siB + st3; e = e > 0.f ? e : 0.2f*e; w13 = __expf(e - miB);
                wsum[rt*2]   += (w00 + w01) + (w02 + w03);
                wsum[rt*2+1] += (w10 + w11) + (w12 + w13);
                split16(w00, w01, ah[rt][0], al[rt][0]);
                split16(w10, w11, ah[rt][1], al[rt][1]);
                split16(w02, w03, ah[rt][2], al[rt][2]);
                split16(w12, w13, ah[rt][3], al[rt][3]);
            }
            #pragma unroll
            for (int ct = 0; ct < 8; ct++) {
                int ba = (ct*8 + g)*36 + ks*8 + t;
                uint32_t b0h = sBh[ba], b1h = sBh[ba + 4];
                uint32_t b0l = sBl[ba], b1l = sBl[ba + 4];
                #pragma unroll
                for (int rt = 0; rt < 2; rt++) {
                    mma16816(C[rt][ct], ah[rt], b0h, b1h);
                    mma16816(C[rt][ct], ah[rt], b0l, b1l);
                    mma16816(C[rt][ct], al[rt], b0h, b1h);
                }
            }
        }
    }
    // row sums: butterfly over the 4 lanes of each group
    float inv[4];
    #pragma unroll
    for (int r = 0; r < 4; r++) {
        float s = wsum[r];
        s += __shfl_xor_sync(0xffffffffu, s, 1);
        s += __shfl_xor_sync(0xffffffffu, s, 2);
        inv[r] = __frcp_rn(s);
    }
    // epilogue
    #pragma unroll
    for (int rt = 0; rt < 2; rt++) {
        int row0 = i0 + wid*32 + rt*16 + g;
        float ia = inv[rt*2], ib = inv[rt*2+1];
        #pragma unroll
        for (int ct = 0; ct < 8; ct++) {
            int col = ct*8 + 2*t;
            float v00 = C[rt][ct][0] * ia, v01 = C[rt][ct][1] * ia;
            float v10 = C[rt][ct][2] * ib, v11 = C[rt][ct][3] * ib;
            if (!LAYER2) {
                v00 = v00 > 0.f ? v00 : expm1f(v00);
                v01 = v01 > 0.f ? v01 : expm1f(v01);
                v10 = v10 > 0.f ? v10 : expm1f(v10);
                v11 = v11 > 0.f ? v11 : expm1f(v11);
            }
            *(float2*)&outp[(size_t)row0*rstride + col]       = make_float2(v00, v01);
            *(float2*)&outp[(size_t)(row0 + 8)*rstride + col] = make_float2(v10, v11);
        }
    }
}

// ---------------- k_gemm2b: Wh2 = x @ W_out (normal + transposed fp16-split) ----------------
__global__ __launch_bounds__(128) void k_gemm2b(const float* __restrict__ Wout) {
    __shared__ float As[64][68];
    __shared__ ull   Bp[32][64];
    int tid = threadIdx.x, m0 = blockIdx.x * 64;
    int rg = tid >> 4, cg = tid & 15;
    ull acc[8][4];
    #pragma unroll
    for (int r = 0; r < 8; r++)
        #pragma unroll
        for (int c = 0; c < 4; c++) acc[r][c] = 0ULL;
    for (int k0 = 0; k0 < 512; k0 += 64) {
        __syncthreads();
        #pragma unroll
        for (int i = 0; i < 8; i++) {
            int l = tid + i*128, row = l >> 4, f4 = l & 15;
            *(float4*)&As[row][f4*4] =
                *(const float4*)&g_x[(size_t)(m0 + row)*512 + k0 + f4*4];
        }
        #pragma unroll
        for (int i = 0; i < 4; i++) {
            int l = tid + i*128, kp = l >> 4, c4 = l & 15;
            float4 f0 = *(const float4*)&Wout[(size_t)(k0 + 2*kp    )*64 + c4*4];
            float4 f1 = *(const float4*)&Wout[(size_t)(k0 + 2*kp + 1)*64 + c4*4];
            *(float4*)&Bp[kp][c4*4]     = make_float4(f0.x, f1.x, f0.y, f1.y);
            *(float4*)&Bp[kp][c4*4 + 2] = make_float4(f0.z, f1.z, f0.w, f1.w);
        }
        __syncthreads();
        #pragma unroll 4
        for (int t = 0; t < 16; t++) {
            ulonglong2 b0 = *(const ulonglong2*)&Bp[2*t  ][cg*4];
            ulonglong2 b0b= *(const ulonglong2*)&Bp[2*t  ][cg*4 + 2];
            ulonglong2 b1 = *(const ulonglong2*)&Bp[2*t+1][cg*4];
            ulonglong2 b1b= *(const ulonglong2*)&Bp[2*t+1][cg*4 + 2];
            #pragma unroll
            for (int r = 0; r < 8; r++) {
                ulonglong2 aq = *(const ulonglong2*)&As[rg*8 + r][t*4];
                ffma2(acc[r][0], aq.x, b0.x);  ffma2(acc[r][1], aq.x, b0.y);
                ffma2(acc[r][2], aq.x, b0b.x); ffma2(acc[r][3], aq.x, b0b.y);
                ffma2(acc[r][0], aq.y, b1.x);  ffma2(acc[r][1], aq.y, b1.y);
                ffma2(acc[r][2], aq.y, b1b.x); ffma2(acc[r][3], aq.y, b1b.y);
            }
        }
    }
    float o[8][4];
    #pragma unroll
    for (int r = 0; r < 8; r++) {
        float2 v0 = f2un(acc[r][0]), v1 = f2un(acc[r][1]);
        float2 v2 = f2un(acc[r][2]), v3 = f2un(acc[r][3]);
        o[r][0] = v0.x + v0.y; o[r][1] = v1.x + v1.y;
        o[r][2] = v2.x + v2.y; o[r][3] = v3.x + v3.y;
        *(float4*)&g_Wh2[(size_t)(m0 + rg*8 + r)*64 + cg*4] =
            make_float4(o[r][0], o[r][1], o[r][2], o[r][3]);
    }
    int jb = (m0 & 511) + rg*8;
    int bq = m0 >> 9;
    #pragma unroll
    for (int q = 0; q < 4; q++) {
        int n = cg*4 + q;
        uint4 Hv, Lv;
        split16(o[0][q], o[1][q], Hv.x, Lv.x);
        split16(o[2][q], o[3][q], Hv.y, Lv.y);
        split16(o[4][q], o[5][q], Hv.z, Lv.z);
        split16(o[6][q], o[7][q], Hv.w, Lv.w);
        size_t idx = ((size_t)bq*64 + n)*256 + (jb >> 1);
        *(uint4*)&g_Wh2T_hi[idx] = Hv;
        *(uint4*)&g_Wh2T_lo[idx] = Lv;
    }
}

// ---------------- k_s2 ----------------
__global__ __launch_bounds__(256) void k_s2(const float* __restrict__ aosrc,
                                            const float* __restrict__ aodst) {
    __shared__ float fs[64][65];
    __shared__ float va[64], vb[64];
    int tid = threadIdx.x, b = blockIdx.x, i0 = blockIdx.y * 64;
    if (tid < 64) { va[tid] = aosrc[tid]; vb[tid] = aodst[tid]; }
    for (int l = tid; l < 4096; l += 256) {
        int r = l >> 6, f = l & 63;
        fs[r][f] = g_Wh2[(size_t)b*32768 + (i0 + r)*64 + f];
    }
    __syncthreads();
    int w = tid >> 5, lane = tid & 31;
    #pragma unroll
    for (int rr = 0; rr < 8; rr++) {
        int row = w*8 + rr;
        float f0 = fs[row][lane], f1 = fs[row][lane + 32];
        float as = f0*va[lane] + f1*va[lane + 32];
        float ad = f0*vb[lane] + f1*vb[lane + 32];
        #pragma unroll
        for (int o = 16; o > 0; o >>= 1) {
            as += __shfl_down_sync(0xffffffffu, as, o);
            ad += __shfl_down_sync(0xffffffffu, ad, o);
        }
        if (lane == 0) {
            g_s2src[b*512 + i0 + row] = as;
            g_s2dst[b*512 + i0 + row] = ad;
        }
    }
}

// ---------------- fc layers ----------------
__global__ __launch_bounds__(256) void k_fc1(const float* __restrict__ w1) {
    __shared__ float zs[32][64];
    __shared__ float ws[64][32];
    int tid = threadIdx.x, ct = blockIdx.x, ks = blockIdx.y;
    int cl = tid & 31, rgq = tid >> 5;
    float acc[4] = {0.f, 0.f, 0.f, 0.f};
    int K0 = ks * 1024;
    for (int kc = 0; kc < 1024; kc += 64) {
        __syncthreads();
        for (int l = tid; l < 2048; l += 256) {
            int r = l >> 6, kk = l & 63;
            zs[r][kk] = g_h2[(size_t)r*32768 + K0 + kc + kk];
        }
        for (int l = tid; l < 2048; l += 256) {
            int kk = l >> 5, c = l & 31;
            ws[kk][c] = w1[(size_t)(K0 + kc + kk)*256 + ct*32 + c];
        }
        __syncthreads();
        #pragma unroll 8
        for (int kk = 0; kk < 64; kk++) {
            float wv = ws[kk][cl];
            #pragma unroll
            for (int r = 0; r < 4; r++) acc[r] += zs[rgq*4 + r][kk] * wv;
        }
    }
    #pragma unroll
    for (int r = 0; r < 4; r++)
        g_fc1part[((size_t)ks*32 + rgq*4 + r)*256 + ct*32 + cl] = acc[r];
}

__global__ void k_fc1red(const float* __restrict__ b1) {
    int b = blockIdx.x, c = threadIdx.x;
    float a = 0.f;
    #pragma unroll 8
    for (int ks = 0; ks < 32; ks++) a += g_fc1part[((size_t)ks*32 + b)*256 + c];
    g_z1[b*256 + c] = fmaxf(a + b1[c], 0.f);
}

__global__ void k_fc2(const float* __restrict__ w2, const float* __restrict__ b2) {
    __shared__ float zr[256];
    int b = blockIdx.x, c = threadIdx.x;
    zr[c] = g_z1[b*256 + c];
    __syncthreads();
    float a = 0.f;
    #pragma unroll 8
    for (int k = 0; k < 256; k++) a += zr[k] * w2[(size_t)k*256 + c];
    g_z2[b*256 + c] = fmaxf(a + b2[c], 0.f);
}

__global__ void k_fc3(const float* __restrict__ w3, const float* __restrict__ b3,
                      float* __restrict__ out) {
    int b = blockIdx.x, tid = threadIdx.x;
    int c = tid >> 5, lane = tid & 31;
    float a = 0.f;
    #pragma unroll
    for (int k = lane; k < 256; k += 32) a += g_z2[b*256 + k] * w3[k*4 + c];
    #pragma unroll
    for (int o = 16; o > 0; o >>= 1) a += __shfl_down_sync(0xffffffffu, a, o);
    if (lane == 0) out[b*4 + c] = tanhf(a + b3[c]);
}

// ---------------- launch ----------------
extern "C" void kernel_launch(void* const* d_in, const int* in_sizes, int n_in,
                              void* d_out, int out_size) {
    const float* state  = (const float*)d_in[0];
    const float* Wheads = (const float*)d_in[1];
    const float* asrc   = (const float*)d_in[2];
    const float* adst   = (const float*)d_in[3];
    const float* Wout   = (const float*)d_in[4];
    const float* aosrc  = (const float*)d_in[5];
    const float* aodst  = (const float*)d_in[6];
    const float* w1     = (const float*)d_in[7];
    const float* b1     = (const float*)d_in[8];
    const float* w2     = (const float*)d_in[9];
    const float* b2     = (const float*)d_in[10];
    const float* w3     = (const float*)d_in[11];
    const float* b3     = (const float*)d_in[12];
    float* out = (float*)d_out;

    k_vheads<<<8, 64>>>(Wheads, asrc, adst);
    k_wh1b  <<<dim3(256, 8), 128>>>(state, Wheads);
    k_s1    <<<dim3(32, 8), 256>>>(state);
    k_attn_mma<false><<<dim3(4, 256), 128>>>();  // layer-1
    k_gemm2b<<<256, 128>>>(Wout);
    k_s2    <<<dim3(32, 8), 256>>>(aosrc, aodst);
    k_attn_mma<true><<<dim3(4, 32), 128>>>();    // layer-2
    k_fc1   <<<dim3(8, 32), 256>>>(w1);
    k_fc1red<<<32, 256>>>(b1);
    k_fc2   <<<32, 256>>>(w2, b2);
    k_fc3   <<<32, 128>>>(w3, b3, out);
}

// round 11
// speedup vs baseline: 2.1761x; 1.0296x over previous
#include <cuda_runtime.h>
#include <cuda_fp16.h>
#include <math.h>
#include <stdint.h>

#define BB 32
#define NN 512
#define FIN 64
#define HH 8
#define HIDD 64
#define OUTF 64

// ---------------- scratch (static __device__, no allocs) ----------------
__device__ uint32_t g_WhT_hi[BB*HH*64*256];  // layer-1 Wh^T, fp16-pair hi (per bh: [n=64][kpair=256])
__device__ uint32_t g_WhT_lo[BB*HH*64*256];  // fp16-pair lo (residual)
__device__ float g_ssrc [BB*HH*NN];
__device__ float g_sdst [BB*HH*NN];
__device__ float g_vsrc [HH*FIN];
__device__ float g_vdst [HH*FIN];
__device__ float g_x    [BB*NN*HH*HIDD];     // layer-1 out, (b,n,h*64+o)
__device__ float g_Wh2  [BB*NN*OUTF];        // normal layout (for k_s2)
__device__ uint32_t g_Wh2T_hi[BB*64*256];    // layer-2 Wh2^T fp16-pair hi
__device__ uint32_t g_Wh2T_lo[BB*64*256];
__device__ float g_s2src[BB*NN];
__device__ float g_s2dst[BB*NN];
__device__ float g_h2   [BB*NN*OUTF];        // layer-2 out == z
__device__ float g_fc1part[32*BB*256];
__device__ float g_z1   [BB*256];
__device__ float g_z2   [BB*256];

using ull = unsigned long long;

__device__ __forceinline__ void ffma2(ull& d, ull a, ull b) {
    asm("fma.rn.f32x2 %0, %1, %2, %0;" : "+l"(d) : "l"(a), "l"(b));
}
__device__ __forceinline__ float2 f2un(ull v) {
    float2 r; asm("mov.b64 {%0, %1}, %2;" : "=f"(r.x), "=f"(r.y) : "l"(v)); return r;
}

// fp16 error-split: (w0,w1) -> hi pair + lo pair (packed f16x2, even k in low half)
__device__ __forceinline__ void split16(float w0, float w1, uint32_t& hi, uint32_t& lo) {
    __half h0 = __float2half_rn(w0), h1 = __float2half_rn(w1);
    __half2 H = __halves2half2(h0, h1);
    hi = *reinterpret_cast<uint32_t*>(&H);
    float r0 = w0 - __half2float(h0);
    float r1 = w1 - __half2float(h1);
    __half2 L = __halves2half2(__float2half_rn(r0), __float2half_rn(r1));
    lo = *reinterpret_cast<uint32_t*>(&L);
}

// warp MMA: D(16x8,f32) += A(16x16,f16) * B(16x8,f16)
__device__ __forceinline__ void mma16816(float* c, const uint32_t* a, uint32_t b0, uint32_t b1) {
    asm volatile(
        "mma.sync.aligned.m16n8k16.row.col.f32.f16.f16.f32 "
        "{%0,%1,%2,%3}, {%4,%5,%6,%7}, {%8,%9}, {%0,%1,%2,%3};"
        : "+f"(c[0]), "+f"(c[1]), "+f"(c[2]), "+f"(c[3])
        : "r"(a[0]), "r"(a[1]), "r"(a[2]), "r"(a[3]), "r"(b0), "r"(b1));
}

// ---------------- k_vheads ----------------
__global__ void k_vheads(const float* __restrict__ Wheads,
                         const float* __restrict__ asrc,
                         const float* __restrict__ adst) {
    int h = blockIdx.x, f = threadIdx.x;
    __shared__ float as[64], ad[64];
    as[f] = asrc[h*64 + f]; ad[f] = adst[h*64 + f];
    __syncthreads();
    float s = 0.f, d = 0.f;
    #pragma unroll 16
    for (int o = 0; o < 64; o++) {
        float wv = Wheads[h*4096 + f*64 + o];
        s += wv * as[o]; d += wv * ad[o];
    }
    g_vsrc[h*64 + f] = s; g_vdst[h*64 + f] = d;
}

// ---------------- k_wh1b: Wh = feat @ W_heads[h] -> transposed fp16-split ----------------
__global__ __launch_bounds__(128) void k_wh1b(const float* __restrict__ A,
                                              const float* __restrict__ Wheads) {
    __shared__ float As[64][68];
    __shared__ ull   Bp[32][64];
    int tid = threadIdx.x;
    int m0 = blockIdx.x * 64;
    int h  = blockIdx.y;
    #pragma unroll
    for (int i = 0; i < 8; i++) {
        int l = tid + i*128, row = l >> 4, f4 = l & 15;
        *(float4*)&As[row][f4*4] = *(const float4*)&A[(size_t)(m0 + row)*64 + f4*4];
    }
    const float* Bg = Wheads + (size_t)h*4096;
    #pragma unroll
    for (int i = 0; i < 4; i++) {
        int l = tid + i*128, kp = l >> 4, c4 = l & 15;
        float4 f0 = *(const float4*)&Bg[(2*kp  )*64 + c4*4];
        float4 f1 = *(const float4*)&Bg[(2*kp+1)*64 + c4*4];
        *(float4*)&Bp[kp][c4*4]     = make_float4(f0.x, f1.x, f0.y, f1.y);
        *(float4*)&Bp[kp][c4*4 + 2] = make_float4(f0.z, f1.z, f0.w, f1.w);
    }
    __syncthreads();
    int rg = tid >> 4, cg = tid & 15;
    ull acc[8][4];
    #pragma unroll
    for (int r = 0; r < 8; r++)
        #pragma unroll
        for (int c = 0; c < 4; c++) acc[r][c] = 0ULL;
    #pragma unroll 4
    for (int t = 0; t < 16; t++) {
        ulonglong2 b0 = *(const ulonglong2*)&Bp[2*t  ][cg*4];
        ulonglong2 b0b= *(const ulonglong2*)&Bp[2*t  ][cg*4 + 2];
        ulonglong2 b1 = *(const ulonglong2*)&Bp[2*t+1][cg*4];
        ulonglong2 b1b= *(const ulonglong2*)&Bp[2*t+1][cg*4 + 2];
        #pragma unroll
        for (int r = 0; r < 8; r++) {
            ulonglong2 aq = *(const ulonglong2*)&As[rg*8 + r][t*4];
            ffma2(acc[r][0], aq.x, b0.x);  ffma2(acc[r][1], aq.x, b0.y);
            ffma2(acc[r][2], aq.x, b0b.x); ffma2(acc[r][3], aq.x, b0b.y);
            ffma2(acc[r][0], aq.y, b1.x);  ffma2(acc[r][1], aq.y, b1.y);
            ffma2(acc[r][2], aq.y, b1b.x); ffma2(acc[r][3], aq.y, b1b.y);
        }
    }
    float o[8][4];
    #pragma unroll
    for (int r = 0; r < 8; r++) {
        float2 v0 = f2un(acc[r][0]), v1 = f2un(acc[r][1]);
        float2 v2 = f2un(acc[r][2]), v3 = f2un(acc[r][3]);
        o[r][0] = v0.x + v0.y; o[r][1] = v1.x + v1.y;
        o[r][2] = v2.x + v2.y; o[r][3] = v3.x + v3.y;
    }
    int jb = (m0 & 511) + rg*8;         // j index (even), 8 consecutive
    int bh = (m0 >> 9)*8 + h;
    #pragma unroll
    for (int q = 0; q < 4; q++) {
        int n = cg*4 + q;
        uint4 Hv, Lv;
        split16(o[0][q], o[1][q], Hv.x, Lv.x);
        split16(o[2][q], o[3][q], Hv.y, Lv.y);
        split16(o[4][q], o[5][q], Hv.z, Lv.z);
        split16(o[6][q], o[7][q], Hv.w, Lv.w);
        size_t idx = ((size_t)bh*64 + n)*256 + (jb >> 1);
        *(uint4*)&g_WhT_hi[idx] = Hv;
        *(uint4*)&g_WhT_lo[idx] = Lv;
    }
}

// ---------------- k_s1 ----------------
__global__ __launch_bounds__(256) void k_s1(const float* __restrict__ state) {
    __shared__ float fs[64][65];
    __shared__ float vs[HH][64], vd[HH][64];
    int tid = threadIdx.x, b = blockIdx.x, i0 = blockIdx.y * 64;
    for (int l = tid; l < 512; l += 256) { vs[l>>6][l&63] = g_vsrc[l]; vd[l>>6][l&63] = g_vdst[l]; }
    for (int l = tid; l < 4096; l += 256) {
        int r = l >> 6, f = l & 63;
        fs[r][f] = state[(size_t)b*32768 + (i0 + r)*64 + f];
    }
    __syncthreads();
    int w = tid >> 5, lane = tid & 31;
    #pragma unroll
    for (int rr = 0; rr < 2; rr++) {
        int row = lane + rr*32;
        float as = 0.f, ad = 0.f;
        #pragma unroll 16
        for (int f = 0; f < 64; f++) {
            float fv = fs[row][f];
            as += fv * vs[w][f]; ad += fv * vd[w][f];
        }
        int idx = (b*8 + w)*512 + i0 + row;
        g_ssrc[idx] = as; g_sdst[idx] = ad;
    }
}

// ---------------- k_attn_mma: softmax(lrelu(s_i+t_j)) @ Wh via mma.sync f16-split ----------------
// exp factorization: lrelu piecewise-linear => w = (s+t>0) ? Ei*Ej : Fi*Fj with
// 1-D precomputed exponentials. Zero MUFU in the hot loop.
template<bool LAYER2>
__global__ __launch_bounds__(128) void k_attn_mma() {
    __shared__ float s_t[512];
    __shared__ float2 sef[512];          // (Ej, Fj)
    __shared__ float red[32];
    __shared__ uint32_t sBh[64*36];      // stride 36 words: conflict-free frag loads
    __shared__ uint32_t sBl[64*36];

    const float* ssrc = LAYER2 ? g_s2src : g_ssrc;
    const float* sdst = LAYER2 ? g_s2dst : g_sdst;
    const uint32_t* BhG0 = LAYER2 ? g_Wh2T_hi : g_WhT_hi;
    const uint32_t* BlG0 = LAYER2 ? g_Wh2T_lo : g_WhT_lo;
    float*       outb = LAYER2 ? g_h2    : g_x;
    const int heads   = LAYER2 ? 1 : 8;
    const int rstride = LAYER2 ? 64 : 512;

    int tid = threadIdx.x, wid = tid >> 5, lane = tid & 31;
    int g = lane >> 2, t = lane & 3;
    int grp = blockIdx.y;
    int i0  = blockIdx.x * 128;
    const uint32_t* BhG = BhG0 + (size_t)grp * 16384;
    const uint32_t* BlG = BlG0 + (size_t)grp * 16384;
    int b = grp / heads, h = grp % heads;
    float* outp = outb + (size_t)b * NN * rstride + h * 64;

    // s_t + block max
    {
        float a0 = sdst[grp*NN + tid];
        float a1 = sdst[grp*NN + tid + 128];
        float a2 = sdst[grp*NN + tid + 256];
        float a3 = sdst[grp*NN + tid + 384];
        s_t[tid] = a0; s_t[tid+128] = a1; s_t[tid+256] = a2; s_t[tid+384] = a3;
        float m = fmaxf(fmaxf(a0, a1), fmaxf(a2, a3));
        #pragma unroll
        for (int o = 16; o > 0; o >>= 1) m = fmaxf(m, __shfl_xor_sync(0xffffffffu, m, o));
        if (lane == 0) red[wid] = m;
    }
    __syncthreads();
    float tmax = fmaxf(fmaxf(red[0], red[1]), fmaxf(red[2], red[3]));

    // 1-D column exponentials (4 per thread, the only j-side MUFU in the kernel)
    #pragma unroll
    for (int k = 0; k < 4; k++) {
        int idx = tid + k*128;
        float d = s_t[idx] - tmax;
        sef[idx] = make_float2(__expf(d), __expf(0.2f*d));
    }

    // per-thread rows: g, g+8, g+16, g+24 (warp-local)
    float si[4], Ei[4], Fi[4];
    #pragma unroll
    for (int r = 0; r < 4; r++) {
        int row = i0 + wid*32 + g + r*8;
        si[r] = ssrc[grp*NN + row];
        float e = si[r] + tmax;             // lrelu monotone => row max
        float m_i = e > 0.f ? e : 0.2f * e;
        Ei[r] = __expf(si[r] + tmax - m_i);
        Fi[r] = __expf(0.2f*(si[r] + tmax) - m_i);
    }

    float C[2][8][4];
    #pragma unroll
    for (int rt = 0; rt < 2; rt++)
        #pragma unroll
        for (int ct = 0; ct < 8; ct++)
            #pragma unroll
            for (int q = 0; q < 4; q++) C[rt][ct][q] = 0.f;
    float wsum[4] = {0.f, 0.f, 0.f, 0.f};

    for (int c = 0; c < 8; c++) {
        __syncthreads();
        // stage B chunk (64 n x 32 kpairs), hi + lo
        #pragma unroll
        for (int i = 0; i < 4; i++) {
            int lin = tid + i*128;
            int n = lin >> 3, q4 = lin & 7;
            *(uint4*)&sBh[n*36 + q4*4] = *(const uint4*)(BhG + (size_t)n*256 + c*32 + q4*4);
            *(uint4*)&sBl[n*36 + q4*4] = *(const uint4*)(BlG + (size_t)n*256 + c*32 + q4*4);
        }
        __syncthreads();
        #pragma unroll
        for (int ks = 0; ks < 4; ks++) {
            int k0 = c*64 + ks*16;
            float st0 = s_t[k0 + 2*t],     st1 = s_t[k0 + 2*t + 1];
            float st2 = s_t[k0 + 2*t + 8], st3 = s_t[k0 + 2*t + 9];
            float2 ef0 = sef[k0 + 2*t],     ef1 = sef[k0 + 2*t + 1];
            float2 ef2 = sef[k0 + 2*t + 8], ef3 = sef[k0 + 2*t + 9];
            uint32_t ah[2][4], al[2][4];
            #pragma unroll
            for (int rt = 0; rt < 2; rt++) {
                float siA = si[rt*2], eA = Ei[rt*2], fA = Fi[rt*2];
                float siB = si[rt*2+1], eB = Ei[rt*2+1], fB = Fi[rt*2+1];
                float w00 = (siA + st0 > 0.f) ? eA*ef0.x : fA*ef0.y;
                float w01 = (siA + st1 > 0.f) ? eA*ef1.x : fA*ef1.y;
                float w02 = (siA + st2 > 0.f) ? eA*ef2.x : fA*ef2.y;
                float w03 = (siA + st3 > 0.f) ? eA*ef3.x : fA*ef3.y;
                float w10 = (siB + st0 > 0.f) ? eB*ef0.x : fB*ef0.y;
                float w11 = (siB + st1 > 0.f) ? eB*ef1.x : fB*ef1.y;
                float w12 = (siB + st2 > 0.f) ? eB*ef2.x : fB*ef2.y;
                float w13 = (siB + st3 > 0.f) ? eB*ef3.x : fB*ef3.y;
                wsum[rt*2]   += (w00 + w01) + (w02 + w03);
                wsum[rt*2+1] += (w10 + w11) + (w12 + w13);
                split16(w00, w01, ah[rt][0], al[rt][0]);
                split16(w10, w11, ah[rt][1], al[rt][1]);
                split16(w02, w03, ah[rt][2], al[rt][2]);
                split16(w12, w13, ah[rt][3], al[rt][3]);
            }
            #pragma unroll
            for (int ct = 0; ct < 8; ct++) {
                int ba = (ct*8 + g)*36 + ks*8 + t;
                uint32_t b0h = sBh[ba], b1h = sBh[ba + 4];
                uint32_t b0l = sBl[ba], b1l = sBl[ba + 4];
                #pragma unroll
                for (int rt = 0; rt < 2; rt++) {
                    mma16816(C[rt][ct], ah[rt], b0h, b1h);
                    mma16816(C[rt][ct], ah[rt], b0l, b1l);
                    mma16816(C[rt][ct], al[rt], b0h, b1h);
                }
            }
        }
    }
    // row sums: butterfly over the 4 lanes of each group
    float inv[4];
    #pragma unroll
    for (int r = 0; r < 4; r++) {
        float s = wsum[r];
        s += __shfl_xor_sync(0xffffffffu, s, 1);
        s += __shfl_xor_sync(0xffffffffu, s, 2);
        inv[r] = __frcp_rn(s);
    }
    // epilogue
    #pragma unroll
    for (int rt = 0; rt < 2; rt++) {
        int row0 = i0 + wid*32 + rt*16 + g;
        float ia = inv[rt*2], ib = inv[rt*2+1];
        #pragma unroll
        for (int ct = 0; ct < 8; ct++) {
            int col = ct*8 + 2*t;
            float v00 = C[rt][ct][0] * ia, v01 = C[rt][ct][1] * ia;
            float v10 = C[rt][ct][2] * ib, v11 = C[rt][ct][3] * ib;
            if (!LAYER2) {
                v00 = v00 > 0.f ? v00 : expm1f(v00);
                v01 = v01 > 0.f ? v01 : expm1f(v01);
                v10 = v10 > 0.f ? v10 : expm1f(v10);
                v11 = v11 > 0.f ? v11 : expm1f(v11);
            }
            *(float2*)&outp[(size_t)row0*rstride + col]       = make_float2(v00, v01);
            *(float2*)&outp[(size_t)(row0 + 8)*rstride + col] = make_float2(v10, v11);
        }
    }
}

// ---------------- k_gemm2b: Wh2 = x @ W_out (normal + transposed fp16-split) ----------------
__global__ __launch_bounds__(128) void k_gemm2b(const float* __restrict__ Wout) {
    __shared__ float As[64][68];
    __shared__ ull   Bp[32][64];
    int tid = threadIdx.x, m0 = blockIdx.x * 64;
    int rg = tid >> 4, cg = tid & 15;
    ull acc[8][4];
    #pragma unroll
    for (int r = 0; r < 8; r++)
        #pragma unroll
        for (int c = 0; c < 4; c++) acc[r][c] = 0ULL;
    for (int k0 = 0; k0 < 512; k0 += 64) {
        __syncthreads();
        #pragma unroll
        for (int i = 0; i < 8; i++) {
            int l = tid + i*128, row = l >> 4, f4 = l & 15;
            *(float4*)&As[row][f4*4] =
                *(const float4*)&g_x[(size_t)(m0 + row)*512 + k0 + f4*4];
        }
        #pragma unroll
        for (int i = 0; i < 4; i++) {
            int l = tid + i*128, kp = l >> 4, c4 = l & 15;
            float4 f0 = *(const float4*)&Wout[(size_t)(k0 + 2*kp    )*64 + c4*4];
            float4 f1 = *(const float4*)&Wout[(size_t)(k0 + 2*kp + 1)*64 + c4*4];
            *(float4*)&Bp[kp][c4*4]     = make_float4(f0.x, f1.x, f0.y, f1.y);
            *(float4*)&Bp[kp][c4*4 + 2] = make_float4(f0.z, f1.z, f0.w, f1.w);
        }
        __syncthreads();
        #pragma unroll 4
        for (int t = 0; t < 16; t++) {
            ulonglong2 b0 = *(const ulonglong2*)&Bp[2*t  ][cg*4];
            ulonglong2 b0b= *(const ulonglong2*)&Bp[2*t  ][cg*4 + 2];
            ulonglong2 b1 = *(const ulonglong2*)&Bp[2*t+1][cg*4];
            ulonglong2 b1b= *(const ulonglong2*)&Bp[2*t+1][cg*4 + 2];
            #pragma unroll
            for (int r = 0; r < 8; r++) {
                ulonglong2 aq = *(const ulonglong2*)&As[rg*8 + r][t*4];
                ffma2(acc[r][0], aq.x, b0.x);  ffma2(acc[r][1], aq.x, b0.y);
                ffma2(acc[r][2], aq.x, b0b.x); ffma2(acc[r][3], aq.x, b0b.y);
                ffma2(acc[r][0], aq.y, b1.x);  ffma2(acc[r][1], aq.y, b1.y);
                ffma2(acc[r][2], aq.y, b1b.x); ffma2(acc[r][3], aq.y, b1b.y);
            }
        }
    }
    float o[8][4];
    #pragma unroll
    for (int r = 0; r < 8; r++) {
        float2 v0 = f2un(acc[r][0]), v1 = f2un(acc[r][1]);
        float2 v2 = f2un(acc[r][2]), v3 = f2un(acc[r][3]);
        o[r][0] = v0.x + v0.y; o[r][1] = v1.x + v1.y;
        o[r][2] = v2.x + v2.y; o[r][3] = v3.x + v3.y;
        *(float4*)&g_Wh2[(size_t)(m0 + rg*8 + r)*64 + cg*4] =
            make_float4(o[r][0], o[r][1], o[r][2], o[r][3]);
    }
    int jb = (m0 & 511) + rg*8;
    int bq = m0 >> 9;
    #pragma unroll
    for (int q = 0; q < 4; q++) {
        int n = cg*4 + q;
        uint4 Hv, Lv;
        split16(o[0][q], o[1][q], Hv.x, Lv.x);
        split16(o[2][q], o[3][q], Hv.y, Lv.y);
        split16(o[4][q], o[5][q], Hv.z, Lv.z);
        split16(o[6][q], o[7][q], Hv.w, Lv.w);
        size_t idx = ((size_t)bq*64 + n)*256 + (jb >> 1);
        *(uint4*)&g_Wh2T_hi[idx] = Hv;
        *(uint4*)&g_Wh2T_lo[idx] = Lv;
    }
}

// ---------------- k_s2 ----------------
__global__ __launch_bounds__(256) void k_s2(const float* __restrict__ aosrc,
                                            const float* __restrict__ aodst) {
    __shared__ float fs[64][65];
    __shared__ float va[64], vb[64];
    int tid = threadIdx.x, b = blockIdx.x, i0 = blockIdx.y * 64;
    if (tid < 64) { va[tid] = aosrc[tid]; vb[tid] = aodst[tid]; }
    for (int l = tid; l < 4096; l += 256) {
        int r = l >> 6, f = l & 63;
        fs[r][f] = g_Wh2[(size_t)b*32768 + (i0 + r)*64 + f];
    }
    __syncthreads();
    int w = tid >> 5, lane = tid & 31;
    #pragma unroll
    for (int rr = 0; rr < 8; rr++) {
        int row = w*8 + rr;
        float f0 = fs[row][lane], f1 = fs[row][lane + 32];
        float as = f0*va[lane] + f1*va[lane + 32];
        float ad = f0*vb[lane] + f1*vb[lane + 32];
        #pragma unroll
        for (int o = 16; o > 0; o >>= 1) {
            as += __shfl_down_sync(0xffffffffu, as, o);
            ad += __shfl_down_sync(0xffffffffu, ad, o);
        }
        if (lane == 0) {
            g_s2src[b*512 + i0 + row] = as;
            g_s2dst[b*512 + i0 + row] = ad;
        }
    }
}

// ---------------- fc layers ----------------
__global__ __launch_bounds__(256) void k_fc1(const float* __restrict__ w1) {
    __shared__ float zs[32][64];
    __shared__ float ws[64][32];
    int tid = threadIdx.x, ct = blockIdx.x, ks = blockIdx.y;
    int cl = tid & 31, rgq = tid >> 5;
    float acc[4] = {0.f, 0.f, 0.f, 0.f};
    int K0 = ks * 1024;
    for (int kc = 0; kc < 1024; kc += 64) {
        __syncthreads();
        for (int l = tid; l < 2048; l += 256) {
            int r = l >> 6, kk = l & 63;
            zs[r][kk] = g_h2[(size_t)r*32768 + K0 + kc + kk];
        }
        for (int l = tid; l < 2048; l += 256) {
            int kk = l >> 5, c = l & 31;
            ws[kk][c] = w1[(size_t)(K0 + kc + kk)*256 + ct*32 + c];
        }
        __syncthreads();
        #pragma unroll 8
        for (int kk = 0; kk < 64; kk++) {
            float wv = ws[kk][cl];
            #pragma unroll
            for (int r = 0; r < 4; r++) acc[r] += zs[rgq*4 + r][kk] * wv;
        }
    }
    #pragma unroll
    for (int r = 0; r < 4; r++)
        g_fc1part[((size_t)ks*32 + rgq*4 + r)*256 + ct*32 + cl] = acc[r];
}

__global__ void k_fc1red(const float* __restrict__ b1) {
    int b = blockIdx.x, c = threadIdx.x;
    float a = 0.f;
    #pragma unroll 8
    for (int ks = 0; ks < 32; ks++) a += g_fc1part[((size_t)ks*32 + b)*256 + c];
    g_z1[b*256 + c] = fmaxf(a + b1[c], 0.f);
}

__global__ void k_fc2(const float* __restrict__ w2, const float* __restrict__ b2) {
    __shared__ float zr[256];
    int b = blockIdx.x, c = threadIdx.x;
    zr[c] = g_z1[b*256 + c];
    __syncthreads();
    float a = 0.f;
    #pragma unroll 8
    for (int k = 0; k < 256; k++) a += zr[k] * w2[(size_t)k*256 + c];
    g_z2[b*256 + c] = fmaxf(a + b2[c], 0.f);
}

__global__ void k_fc3(const float* __restrict__ w3, const float* __restrict__ b3,
                      float* __restrict__ out) {
    int b = blockIdx.x, tid = threadIdx.x;
    int c = tid >> 5, lane = tid & 31;
    float a = 0.f;
    #pragma unroll
    for (int k = lane; k < 256; k += 32) a += g_z2[b*256 + k] * w3[k*4 + c];
    #pragma unroll
    for (int o = 16; o > 0; o >>= 1) a += __shfl_down_sync(0xffffffffu, a, o);
    if (lane == 0) out[b*4 + c] = tanhf(a + b3[c]);
}

// ---------------- launch ----------------
extern "C" void kernel_launch(void* const* d_in, const int* in_sizes, int n_in,
                              void* d_out, int out_size) {
    const float* state  = (const float*)d_in[0];
    const float* Wheads = (const float*)d_in[1];
    const float* asrc   = (const float*)d_in[2];
    const float* adst   = (const float*)d_in[3];
    const float* Wout   = (const float*)d_in[4];
    const float* aosrc  = (const float*)d_in[5];
    const float* aodst  = (const float*)d_in[6];
    const float* w1     = (const float*)d_in[7];
    const float* b1     = (const float*)d_in[8];
    const float* w2     = (const float*)d_in[9];
    const float* b2     = (const float*)d_in[10];
    const float* w3     = (const float*)d_in[11];
    const float* b3     = (const float*)d_in[12];
    float* out = (float*)d_out;

    k_vheads<<<8, 64>>>(Wheads, asrc, adst);
    k_wh1b  <<<dim3(256, 8), 128>>>(state, Wheads);
    k_s1    <<<dim3(32, 8), 256>>>(state);
    k_attn_mma<false><<<dim3(4, 256), 128>>>();  // layer-1
    k_gemm2b<<<256, 128>>>(Wout);
    k_s2    <<<dim3(32, 8), 256>>>(aosrc, aodst);
    k_attn_mma<true><<<dim3(4, 32), 128>>>();    // layer-2
    k_fc1   <<<dim3(8, 32), 256>>>(w1);
    k_fc1red<<<32, 256>>>(b1);
    k_fc2   <<<32, 256>>>(w2, b2);
    k_fc3   <<<32, 128>>>(w3, b3, out);
}

// round 12
// speedup vs baseline: 2.2787x; 1.0472x over previous
#include <cuda_runtime.h>
#include <cuda_fp16.h>
#include <math.h>
#include <stdint.h>

#define BB 32
#define NN 512
#define FIN 64
#define HH 8
#define HIDD 64
#define OUTF 64

// ---------------- scratch (static __device__, no allocs) ----------------
__device__ uint32_t g_WhT_hi[BB*HH*64*256];  // layer-1 Wh^T, fp16-pair hi (per bh: [n=64][jpair=256])
__device__ uint32_t g_WhT_lo[BB*HH*64*256];
__device__ float g_ssrc [BB*HH*NN];
__device__ float g_sdst [BB*HH*NN];
__device__ float g_vsrc [HH*FIN];
__device__ float g_vdst [HH*FIN];
__device__ uint32_t g_st_hi[16384*32];       // split state [m][kpair=32]
__device__ uint32_t g_st_lo[16384*32];
__device__ uint32_t g_WhdT_hi[HH*64*32];     // split W_heads^T [h][o][fpair=32]
__device__ uint32_t g_WhdT_lo[HH*64*32];
__device__ uint32_t g_WoutT_hi[64*256];      // split W_out^T [n][kpair=256]
__device__ uint32_t g_WoutT_lo[64*256];
__device__ uint32_t g_x_hi[16384*256];       // layer-1 out split pairs [m][kpair=256]
__device__ uint32_t g_x_lo[16384*256];
__device__ float g_Wh2  [BB*NN*OUTF];        // normal layout (for k_s2)
__device__ uint32_t g_Wh2T_hi[BB*64*256];    // layer-2 Wh2^T fp16-pair hi
__device__ uint32_t g_Wh2T_lo[BB*64*256];
__device__ float g_s2src[BB*NN];
__device__ float g_s2dst[BB*NN];
__device__ float g_h2   [BB*NN*OUTF];        // layer-2 out == z
__device__ float g_fc1part[32*BB*256];
__device__ float g_z1   [BB*256];
__device__ float g_z2   [BB*256];

// fp16 error-split: (w0,w1) -> hi pair + lo pair (packed f16x2, even k in low half)
__device__ __forceinline__ void split16(float w0, float w1, uint32_t& hi, uint32_t& lo) {
    __half h0 = __float2half_rn(w0), h1 = __float2half_rn(w1);
    __half2 H = __halves2half2(h0, h1);
    hi = *reinterpret_cast<uint32_t*>(&H);
    float r0 = w0 - __half2float(h0);
    float r1 = w1 - __half2float(h1);
    __half2 L = __halves2half2(__float2half_rn(r0), __float2half_rn(r1));
    lo = *reinterpret_cast<uint32_t*>(&L);
}

// warp MMA: D(16x8,f32) += A(16x16,f16) * B(16x8,f16)
__device__ __forceinline__ void mma16816(float* c, const uint32_t* a, uint32_t b0, uint32_t b1) {
    asm volatile(
        "mma.sync.aligned.m16n8k16.row.col.f32.f16.f16.f32 "
        "{%0,%1,%2,%3}, {%4,%5,%6,%7}, {%8,%9}, {%0,%1,%2,%3};"
        : "+f"(c[0]), "+f"(c[1]), "+f"(c[2]), "+f"(c[3])
        : "r"(a[0]), "r"(a[1]), "r"(a[2]), "r"(a[3]), "r"(b0), "r"(b1));
}

// ---------------- prep: k_vheads + W_heads split ----------------
__global__ void k_vheads(const float* __restrict__ Wheads,
                         const float* __restrict__ asrc,
                         const float* __restrict__ adst) {
    int h = blockIdx.x, f = threadIdx.x;
    __shared__ float as[64], ad[64];
    as[f] = asrc[h*64 + f]; ad[f] = adst[h*64 + f];
    __syncthreads();
    float s = 0.f, d = 0.f;
    #pragma unroll 16
    for (int o = 0; o < 64; o++) {
        float wv = Wheads[h*4096 + f*64 + o];
        s += wv * as[o]; d += wv * ad[o];
    }
    g_vsrc[h*64 + f] = s; g_vdst[h*64 + f] = d;
    // split W_heads^T: thread = o, pairs along f
    int o = f;
    for (int fp = 0; fp < 32; fp++) {
        float w0 = Wheads[h*4096 + (2*fp    )*64 + o];
        float w1 = Wheads[h*4096 + (2*fp + 1)*64 + o];
        uint32_t hi, lo; split16(w0, w1, hi, lo);
        g_WhdT_hi[h*2048 + o*32 + fp] = hi;
        g_WhdT_lo[h*2048 + o*32 + fp] = lo;
    }
}

// ---------------- prep: split state ----------------
__global__ __launch_bounds__(256) void k_split_state(const float* __restrict__ state) {
    int idx = blockIdx.x*256 + threadIdx.x;
    for (int p = idx; p < 16384*32; p += gridDim.x*256) {
        float2 v = *(const float2*)&state[2*p];
        uint32_t hi, lo; split16(v.x, v.y, hi, lo);
        g_st_hi[p] = hi; g_st_lo[p] = lo;
    }
}

// ---------------- prep: split W_out^T ----------------
__global__ __launch_bounds__(256) void k_split_wout(const float* __restrict__ Wout) {
    int lin = blockIdx.x*256 + threadIdx.x;   // 16384
    int kp = lin >> 6, n = lin & 63;
    float w0 = Wout[(2*kp    )*64 + n];
    float w1 = Wout[(2*kp + 1)*64 + n];
    uint32_t hi, lo; split16(w0, w1, hi, lo);
    g_WoutT_hi[n*256 + kp] = hi;
    g_WoutT_lo[n*256 + kp] = lo;
}

// ---------------- k_s1 ----------------
__global__ __launch_bounds__(256) void k_s1(const float* __restrict__ state) {
    __shared__ float fs[64][65];
    __shared__ float vs[HH][64], vd[HH][64];
    int tid = threadIdx.x, b = blockIdx.x, i0 = blockIdx.y * 64;
    for (int l = tid; l < 512; l += 256) { vs[l>>6][l&63] = g_vsrc[l]; vd[l>>6][l&63] = g_vdst[l]; }
    for (int l = tid; l < 4096; l += 256) {
        int r = l >> 6, f = l & 63;
        fs[r][f] = state[(size_t)b*32768 + (i0 + r)*64 + f];
    }
    __syncthreads();
    int w = tid >> 5, lane = tid & 31;
    #pragma unroll
    for (int rr = 0; rr < 2; rr++) {
        int row = lane + rr*32;
        float as = 0.f, ad = 0.f;
        #pragma unroll 16
        for (int f = 0; f < 64; f++) {
            float fv = fs[row][f];
            as += fv * vs[w][f]; ad += fv * vd[w][f];
        }
        int idx = (b*8 + w)*512 + i0 + row;
        g_ssrc[idx] = as; g_sdst[idx] = ad;
    }
}

// ---------------- k_gemmT: unified mma.sync producer GEMM ----------------
// C[M=16384(or per-head), N=64] = A @ B with A fp16-split pairs [m][KP],
// B fp16-split transposed [n][KP]. Output: split-transposed [n][jpair] (+fp32 for gemm2).
// Block: 128 thr, 64 rows; warp = 16 rows (rt=1), 8 ct tiles of n8, 4 ksteps/chunk.
template<bool WH1>
__global__ __launch_bounds__(128) void k_gemmT() {
    constexpr int KP  = WH1 ? 32 : 256;
    constexpr int NCH = KP / 32;
    __shared__ uint32_t sraw[64*36*2];            // B stage; reused as fp32 C-transpose buffer
    uint32_t* sBh = sraw;
    uint32_t* sBl = sraw + 64*36;
    float*    sC  = (float*)sraw;

    int tid = threadIdx.x, wid = tid >> 5, lane = tid & 31;
    int g = lane >> 2, t = lane & 3;
    int m0 = blockIdx.x * 64;
    int h  = blockIdx.y;

    const uint32_t *Ah, *Al, *Bh, *Bl;
    uint32_t *oTh, *oTl;
    int grp;
    if (WH1) {
        Ah = g_st_hi; Al = g_st_lo;
        Bh = g_WhdT_hi + h*2048; Bl = g_WhdT_lo + h*2048;
        oTh = g_WhT_hi; oTl = g_WhT_lo;
        grp = (m0 >> 9)*8 + h;
    } else {
        Ah = g_x_hi; Al = g_x_lo;
        Bh = g_WoutT_hi; Bl = g_WoutT_lo;
        oTh = g_Wh2T_hi; oTl = g_Wh2T_lo;
        grp = m0 >> 9;
    }
    int r0 = m0 + wid*16 + g, r1 = r0 + 8;

    float C[8][4];
    #pragma unroll
    for (int ct = 0; ct < 8; ct++)
        #pragma unroll
        for (int q = 0; q < 4; q++) C[ct][q] = 0.f;

    for (int c = 0; c < NCH; c++) {
        __syncthreads();
        #pragma unroll
        for (int i = 0; i < 4; i++) {            // stage B chunk: 64n x 32kp, hi+lo
            int lin = tid + i*128;
            int n = lin >> 3, q4 = lin & 7;
            *(uint4*)&sBh[n*36 + q4*4] = *(const uint4*)(Bh + (size_t)n*KP + c*32 + q4*4);
            *(uint4*)&sBl[n*36 + q4*4] = *(const uint4*)(Bl + (size_t)n*KP + c*32 + q4*4);
        }
        __syncthreads();
        #pragma unroll
        for (int s = 0; s < 4; s++) {
            int kp = c*32 + 8*s + t;
            uint32_t aH[4] = { Ah[(size_t)r0*KP + kp],     Ah[(size_t)r1*KP + kp],
                               Ah[(size_t)r0*KP + kp + 4], Ah[(size_t)r1*KP + kp + 4] };
            uint32_t aL[4] = { Al[(size_t)r0*KP + kp],     Al[(size_t)r1*KP + kp],
                               Al[(size_t)r0*KP + kp + 4], Al[(size_t)r1*KP + kp + 4] };
            #pragma unroll
            for (int ct = 0; ct < 8; ct++) {
                int ba = (ct*8 + g)*36 + s*8 + t;
                uint32_t b0h = sBh[ba], b1h = sBh[ba + 4];
                uint32_t b0l = sBl[ba], b1l = sBl[ba + 4];
                mma16816(C[ct], aH, b0h, b1h);
                mma16816(C[ct], aH, b0l, b1l);
                mma16816(C[ct], aL, b0h, b1h);
            }
        }
    }
    if (!WH1) {                                  // fp32 out for k_s2
        #pragma unroll
        for (int ct = 0; ct < 8; ct++) {
            *(float2*)&g_Wh2[(size_t)r0*64 + ct*8 + 2*t] = make_float2(C[ct][0], C[ct][1]);
            *(float2*)&g_Wh2[(size_t)r1*64 + ct*8 + 2*t] = make_float2(C[ct][2], C[ct][3]);
        }
    }
    __syncthreads();                             // done with sB
    {
        int rl0 = wid*16 + g;
        #pragma unroll
        for (int ct = 0; ct < 8; ct++) {
            *(float2*)&sC[rl0*68 + ct*8 + 2*t]      = make_float2(C[ct][0], C[ct][1]);
            *(float2*)&sC[(rl0+8)*68 + ct*8 + 2*t]  = make_float2(C[ct][2], C[ct][3]);
        }
    }
    __syncthreads();
    int jb0 = (m0 & 511) >> 1;
    #pragma unroll
    for (int i = 0; i < 16; i++) {
        int lin = tid + i*128;
        int n = lin >> 5, jp = lin & 31;
        float v0 = sC[(2*jp)*68 + n], v1 = sC[(2*jp+1)*68 + n];
        uint32_t hi, lo; split16(v0, v1, hi, lo);
        size_t oidx = (size_t)grp*16384 + n*256 + jb0 + jp;
        oTh[oidx] = hi; oTl[oidx] = lo;
    }
}

// ---------------- k_attn_mma: softmax(lrelu(s_i+t_j)) @ Wh via mma.sync f16-split ----------------
template<bool LAYER2>
__global__ __launch_bounds__(128) void k_attn_mma() {
    __shared__ float s_t[512];
    __shared__ float2 sef[512];          // (Ej, Fj)
    __shared__ float red[32];
    __shared__ uint32_t sBh[64*36];
    __shared__ uint32_t sBl[64*36];

    const float* ssrc = LAYER2 ? g_s2src : g_ssrc;
    const float* sdst = LAYER2 ? g_s2dst : g_sdst;
    const uint32_t* BhG0 = LAYER2 ? g_Wh2T_hi : g_WhT_hi;
    const uint32_t* BlG0 = LAYER2 ? g_Wh2T_lo : g_WhT_lo;
    const int heads   = LAYER2 ? 1 : 8;

    int tid = threadIdx.x, wid = tid >> 5, lane = tid & 31;
    int g = lane >> 2, t = lane & 3;
    int grp = blockIdx.y;
    int i0  = blockIdx.x * 128;
    const uint32_t* BhG = BhG0 + (size_t)grp * 16384;
    const uint32_t* BlG = BlG0 + (size_t)grp * 16384;
    int b = grp / heads, h = grp % heads;

    // s_t + block max
    {
        float a0 = sdst[grp*NN + tid];
        float a1 = sdst[grp*NN + tid + 128];
        float a2 = sdst[grp*NN + tid + 256];
        float a3 = sdst[grp*NN + tid + 384];
        s_t[tid] = a0; s_t[tid+128] = a1; s_t[tid+256] = a2; s_t[tid+384] = a3;
        float m = fmaxf(fmaxf(a0, a1), fmaxf(a2, a3));
        #pragma unroll
        for (int o = 16; o > 0; o >>= 1) m = fmaxf(m, __shfl_xor_sync(0xffffffffu, m, o));
        if (lane == 0) red[wid] = m;
    }
    __syncthreads();
    float tmax = fmaxf(fmaxf(red[0], red[1]), fmaxf(red[2], red[3]));

    #pragma unroll
    for (int k = 0; k < 4; k++) {
        int idx = tid + k*128;
        float d = s_t[idx] - tmax;
        sef[idx] = make_float2(__expf(d), __expf(0.2f*d));
    }

    float si[4], Ei[4], Fi[4];
    #pragma unroll
    for (int r = 0; r < 4; r++) {
        int row = i0 + wid*32 + g + r*8;
        si[r] = ssrc[grp*NN + row];
        float e = si[r] + tmax;
        float m_i = e > 0.f ? e : 0.2f * e;
        Ei[r] = __expf(si[r] + tmax - m_i);
        Fi[r] = __expf(0.2f*(si[r] + tmax) - m_i);
    }

    float C[2][8][4];
    #pragma unroll
    for (int rt = 0; rt < 2; rt++)
        #pragma unroll
        for (int ct = 0; ct < 8; ct++)
            #pragma unroll
            for (int q = 0; q < 4; q++) C[rt][ct][q] = 0.f;
    float wsum[4] = {0.f, 0.f, 0.f, 0.f};

    for (int c = 0; c < 8; c++) {
        __syncthreads();
        #pragma unroll
        for (int i = 0; i < 4; i++) {
            int lin = tid + i*128;
            int n = lin >> 3, q4 = lin & 7;
            *(uint4*)&sBh[n*36 + q4*4] = *(const uint4*)(BhG + (size_t)n*256 + c*32 + q4*4);
            *(uint4*)&sBl[n*36 + q4*4] = *(const uint4*)(BlG + (size_t)n*256 + c*32 + q4*4);
        }
        __syncthreads();
        #pragma unroll
        for (int ks = 0; ks < 4; ks++) {
            int k0 = c*64 + ks*16;
            float st0 = s_t[k0 + 2*t],     st1 = s_t[k0 + 2*t + 1];
            float st2 = s_t[k0 + 2*t + 8], st3 = s_t[k0 + 2*t + 9];
            float2 ef0 = sef[k0 + 2*t],     ef1 = sef[k0 + 2*t + 1];
            float2 ef2 = sef[k0 + 2*t + 8], ef3 = sef[k0 + 2*t + 9];
            uint32_t ah[2][4], al[2][4];
            #pragma unroll
            for (int rt = 0; rt < 2; rt++) {
                float siA = si[rt*2], eA = Ei[rt*2], fA = Fi[rt*2];
                float siB = si[rt*2+1], eB = Ei[rt*2+1], fB = Fi[rt*2+1];
                float w00 = (siA + st0 > 0.f) ? eA*ef0.x : fA*ef0.y;
                float w01 = (siA + st1 > 0.f) ? eA*ef1.x : fA*ef1.y;
                float w02 = (siA + st2 > 0.f) ? eA*ef2.x : fA*ef2.y;
                float w03 = (siA + st3 > 0.f) ? eA*ef3.x : fA*ef3.y;
                float w10 = (siB + st0 > 0.f) ? eB*ef0.x : fB*ef0.y;
                float w11 = (siB + st1 > 0.f) ? eB*ef1.x : fB*ef1.y;
                float w12 = (siB + st2 > 0.f) ? eB*ef2.x : fB*ef2.y;
                float w13 = (siB + st3 > 0.f) ? eB*ef3.x : fB*ef3.y;
                wsum[rt*2]   += (w00 + w01) + (w02 + w03);
                wsum[rt*2+1] += (w10 + w11) + (w12 + w13);
                split16(w00, w01, ah[rt][0], al[rt][0]);
                split16(w10, w11, ah[rt][1], al[rt][1]);
                split16(w02, w03, ah[rt][2], al[rt][2]);
                split16(w12, w13, ah[rt][3], al[rt][3]);
            }
            #pragma unroll
            for (int ct = 0; ct < 8; ct++) {
                int ba = (ct*8 + g)*36 + ks*8 + t;
                uint32_t b0h = sBh[ba], b1h = sBh[ba + 4];
                uint32_t b0l = sBl[ba], b1l = sBl[ba + 4];
                #pragma unroll
                for (int rt = 0; rt < 2; rt++) {
                    mma16816(C[rt][ct], ah[rt], b0h, b1h);
                    mma16816(C[rt][ct], ah[rt], b0l, b1l);
                    mma16816(C[rt][ct], al[rt], b0h, b1h);
                }
            }
        }
    }
    float inv[4];
    #pragma unroll
    for (int r = 0; r < 4; r++) {
        float s = wsum[r];
        s += __shfl_xor_sync(0xffffffffu, s, 1);
        s += __shfl_xor_sync(0xffffffffu, s, 2);
        inv[r] = __frcp_rn(s);
    }
    #pragma unroll
    for (int rt = 0; rt < 2; rt++) {
        int row0 = i0 + wid*32 + rt*16 + g;
        float ia = inv[rt*2], ib = inv[rt*2+1];
        #pragma unroll
        for (int ct = 0; ct < 8; ct++) {
            float v00 = C[rt][ct][0] * ia, v01 = C[rt][ct][1] * ia;
            float v10 = C[rt][ct][2] * ib, v11 = C[rt][ct][3] * ib;
            if (!LAYER2) {
                v00 = v00 > 0.f ? v00 : expm1f(v00);
                v01 = v01 > 0.f ? v01 : expm1f(v01);
                v10 = v10 > 0.f ? v10 : expm1f(v10);
                v11 = v11 > 0.f ? v11 : expm1f(v11);
                // store split pairs into g_x (consumed by gemm2 as A frags)
                uint32_t hi, lo;
                size_t xi = (size_t)(b*512 + row0)*256 + h*32 + ct*4 + t;
                split16(v00, v01, hi, lo);
                g_x_hi[xi] = hi; g_x_lo[xi] = lo;
                split16(v10, v11, hi, lo);
                g_x_hi[xi + 8*256] = hi; g_x_lo[xi + 8*256] = lo;
            } else {
                int col = ct*8 + 2*t;
                float* outp = g_h2 + (size_t)b * NN * 64;
                *(float2*)&outp[(size_t)row0*64 + col]       = make_float2(v00, v01);
                *(float2*)&outp[(size_t)(row0 + 8)*64 + col] = make_float2(v10, v11);
            }
        }
    }
}

// ---------------- k_s2 ----------------
__global__ __launch_bounds__(256) void k_s2(const float* __restrict__ aosrc,
                                            const float* __restrict__ aodst) {
    __shared__ float fs[64][65];
    __shared__ float va[64], vb[64];
    int tid = threadIdx.x, b = blockIdx.x, i0 = blockIdx.y * 64;
    if (tid < 64) { va[tid] = aosrc[tid]; vb[tid] = aodst[tid]; }
    for (int l = tid; l < 4096; l += 256) {
        int r = l >> 6, f = l & 63;
        fs[r][f] = g_Wh2[(size_t)b*32768 + (i0 + r)*64 + f];
    }
    __syncthreads();
    int w = tid >> 5, lane = tid & 31;
    #pragma unroll
    for (int rr = 0; rr < 8; rr++) {
        int row = w*8 + rr;
        float f0 = fs[row][lane], f1 = fs[row][lane + 32];
        float as = f0*va[lane] + f1*va[lane + 32];
        float ad = f0*vb[lane] + f1*vb[lane + 32];
        #pragma unroll
        for (int o = 16; o > 0; o >>= 1) {
            as += __shfl_down_sync(0xffffffffu, as, o);
            ad += __shfl_down_sync(0xffffffffu, ad, o);
        }
        if (lane == 0) {
            g_s2src[b*512 + i0 + row] = as;
            g_s2dst[b*512 + i0 + row] = ad;
        }
    }
}

// ---------------- fc layers ----------------
__global__ __launch_bounds__(256) void k_fc1(const float* __restrict__ w1) {
    __shared__ float zs[32][64];
    __shared__ float ws[64][32];
    int tid = threadIdx.x, ct = blockIdx.x, ks = blockIdx.y;
    int cl = tid & 31, rgq = tid >> 5;
    float acc[4] = {0.f, 0.f, 0.f, 0.f};
    int K0 = ks * 1024;
    for (int kc = 0; kc < 1024; kc += 64) {
        __syncthreads();
        for (int l = tid; l < 2048; l += 256) {
            int r = l >> 6, kk = l & 63;
            zs[r][kk] = g_h2[(size_t)r*32768 + K0 + kc + kk];
        }
        for (int l = tid; l < 2048; l += 256) {
            int kk = l >> 5, c = l & 31;
            ws[kk][c] = w1[(size_t)(K0 + kc + kk)*256 + ct*32 + c];
        }
        __syncthreads();
        #pragma unroll 8
        for (int kk = 0; kk < 64; kk++) {
            float wv = ws[kk][cl];
            #pragma unroll
            for (int r = 0; r < 4; r++) acc[r] += zs[rgq*4 + r][kk] * wv;
        }
    }
    #pragma unroll
    for (int r = 0; r < 4; r++)
        g_fc1part[((size_t)ks*32 + rgq*4 + r)*256 + ct*32 + cl] = acc[r];
}

__global__ void k_fc1red(const float* __restrict__ b1) {
    int b = blockIdx.x, c = threadIdx.x;
    float a = 0.f;
    #pragma unroll 8
    for (int ks = 0; ks < 32; ks++) a += g_fc1part[((size_t)ks*32 + b)*256 + c];
    g_z1[b*256 + c] = fmaxf(a + b1[c], 0.f);
}

__global__ void k_fc2(const float* __restrict__ w2, const float* __restrict__ b2) {
    __shared__ float zr[256];
    int b = blockIdx.x, c = threadIdx.x;
    zr[c] = g_z1[b*256 + c];
    __syncthreads();
    float a = 0.f;
    #pragma unroll 8
    for (int k = 0; k < 256; k++) a += zr[k] * w2[(size_t)k*256 + c];
    g_z2[b*256 + c] = fmaxf(a + b2[c], 0.f);
}

__global__ void k_fc3(const float* __restrict__ w3, const float* __restrict__ b3,
                      float* __restrict__ out) {
    int b = blockIdx.x, tid = threadIdx.x;
    int c = tid >> 5, lane = tid & 31;
    float a = 0.f;
    #pragma unroll
    for (int k = lane; k < 256; k += 32) a += g_z2[b*256 + k] * w3[k*4 + c];
    #pragma unroll
    for (int o = 16; o > 0; o >>= 1) a += __shfl_down_sync(0xffffffffu, a, o);
    if (lane == 0) out[b*4 + c] = tanhf(a + b3[c]);
}

// ---------------- launch ----------------
extern "C" void kernel_launch(void* const* d_in, const int* in_sizes, int n_in,
                              void* d_out, int out_size) {
    const float* state  = (const float*)d_in[0];
    const float* Wheads = (const float*)d_in[1];
    const float* asrc   = (const float*)d_in[2];
    const float* adst   = (const float*)d_in[3];
    const float* Wout   = (const float*)d_in[4];
    const float* aosrc  = (const float*)d_in[5];
    const float* aodst  = (const float*)d_in[6];
    const float* w1     = (const float*)d_in[7];
    const float* b1     = (const float*)d_in[8];
    const float* w2     = (const float*)d_in[9];
    const float* b2     = (const float*)d_in[10];
    const float* w3     = (const float*)d_in[11];
    const float* b3     = (const float*)d_in[12];
    float* out = (float*)d_out;

    k_vheads     <<<8, 64>>>(Wheads, asrc, adst);
    k_split_state<<<512, 256>>>(state);
    k_split_wout <<<64, 256>>>(Wout);
    k_gemmT<true><<<dim3(256, 8), 128>>>();      // Wh = feat @ W_heads  (tensor)
    k_s1         <<<dim3(32, 8), 256>>>(state);
    k_attn_mma<false><<<dim3(4, 256), 128>>>();  // layer-1 attention
    k_gemmT<false><<<256, 128>>>();              // Wh2 = x @ W_out      (tensor)
    k_s2         <<<dim3(32, 8), 256>>>(aosrc, aodst);
    k_attn_mma<true><<<dim3(4, 32), 128>>>();    // layer-2 attention
    k_fc1        <<<dim3(8, 32), 256>>>(w1);
    k_fc1red     <<<32, 256>>>(b1);
    k_fc2        <<<32, 256>>>(w2, b2);
    k_fc3        <<<32, 128>>>(w3, b3, out);
}